// round 1
// baseline (speedup 1.0000x reference)
#include <cuda_runtime.h>
#include <cuda_bf16.h>
#include <math.h>

#define N      8192
#define DIM    128
#define NCLS   64
#define BM     64
#define BN     64
#define MAXMEM 8192   // safety bound on members per class

// ---------------- scratch (device globals; no allocation) ----------------
__device__ float g_sq[N];
__device__ float g_Zpart[2][N];
__device__ int   g_class_members[NCLS][MAXMEM];
__device__ int   g_class_count[NCLS];
__device__ float g_label_mean[NCLS];
__device__ int   g_label_valid[NCLS];

// ---------------- kernel A: row squared norms ----------------
__global__ void sq_kernel(const float* __restrict__ emb) {
    int i = blockIdx.x * blockDim.x + threadIdx.x;
    if (i >= N) return;
    const float4* row = reinterpret_cast<const float4*>(emb + (size_t)i * DIM);
    float s = 0.f;
#pragma unroll
    for (int t = 0; t < DIM / 4; ++t) {
        float4 v = row[t];
        s += v.x * v.x + v.y * v.y + v.z * v.z + v.w * v.w;
    }
    g_sq[i] = s;
}

// ---------------- kernel B: per-class member lists (deterministic, ascending) ----------------
__global__ void classes_kernel(const int* __restrict__ labels) {
    int c = blockIdx.x;        // one warp per class
    int lane = threadIdx.x;    // 0..31
    int cnt = 0;
    for (int base = 0; base < N; base += 32) {
        int l = labels[base + lane];
        bool mine = (l == c);
        unsigned mask = __ballot_sync(0xffffffffu, mine);
        if (mine) {
            int pos = cnt + __popc(mask & ((1u << lane) - 1u));
            g_class_members[c][pos] = base + lane;
        }
        cnt += __popc(mask);
    }
    if (lane == 0) g_class_count[c] = cnt;
}

// ---------------- kernel C: Z[i] = sum over negatives of exp(D[i,j]) ----------------
// grid: (N/BM row tiles, 2 column halves); 256 threads as 16x16, 4x4 microtile.
__global__ __launch_bounds__(256, 2)
void z_kernel(const float* __restrict__ emb, const int* __restrict__ labels) {
    __shared__ float As[DIM][BM];   // k-major A tile (rows of this block)
    __shared__ float Bs[DIM][BN];   // k-major B tile (current column tile)
    __shared__ int   lr[BM];
    __shared__ int   lc[BN];
    __shared__ float red[BM][17];   // cross-thread row reduction (padded)

    const int r0    = blockIdx.x * BM;
    const int half  = blockIdx.y;
    const int cbeg  = half * (N / 2);
    const int cend  = cbeg + (N / 2);

    const int tid = threadIdx.x;
    const int tx  = tid & 15;
    const int ty  = tid >> 4;

    // load A tile (64 rows x 128 dims), transpose to k-major
    for (int s = tid; s < BM * (DIM / 4); s += 256) {
        int row = s >> 5;          // 32 float4 per row
        int c4  = s & 31;
        float4 v = reinterpret_cast<const float4*>(emb + (size_t)(r0 + row) * DIM)[c4];
        int k = c4 * 4;
        As[k + 0][row] = v.x;
        As[k + 1][row] = v.y;
        As[k + 2][row] = v.z;
        As[k + 3][row] = v.w;
    }
    if (tid < BM) lr[tid] = labels[r0 + tid];
    __syncthreads();

    float sqi[4];
    int   myl[4];
    float rowacc[4] = {0.f, 0.f, 0.f, 0.f};
#pragma unroll
    for (int ri = 0; ri < 4; ++ri) {
        sqi[ri] = g_sq[r0 + ty * 4 + ri];
        myl[ri] = lr[ty * 4 + ri];
    }

    for (int c0 = cbeg; c0 < cend; c0 += BN) {
        __syncthreads();  // previous tile's compute done before overwriting Bs
        for (int s = tid; s < BN * (DIM / 4); s += 256) {
            int row = s >> 5;
            int c4  = s & 31;
            float4 v = reinterpret_cast<const float4*>(emb + (size_t)(c0 + row) * DIM)[c4];
            int k = c4 * 4;
            Bs[k + 0][row] = v.x;
            Bs[k + 1][row] = v.y;
            Bs[k + 2][row] = v.z;
            Bs[k + 3][row] = v.w;
        }
        if (tid < BN) lc[tid] = labels[c0 + tid];
        __syncthreads();

        float acc[4][4];
#pragma unroll
        for (int ri = 0; ri < 4; ++ri)
#pragma unroll
            for (int ci = 0; ci < 4; ++ci) acc[ri][ci] = 0.f;

#pragma unroll 8
        for (int k = 0; k < DIM; ++k) {
            float4 a = *reinterpret_cast<const float4*>(&As[k][ty * 4]);
            float4 b = *reinterpret_cast<const float4*>(&Bs[k][tx * 4]);
            float av[4] = {a.x, a.y, a.z, a.w};
            float bv[4] = {b.x, b.y, b.z, b.w};
#pragma unroll
            for (int ri = 0; ri < 4; ++ri)
#pragma unroll
                for (int ci = 0; ci < 4; ++ci)
                    acc[ri][ci] = fmaf(av[ri], bv[ci], acc[ri][ci]);
        }

        // epilogue: exp + negative mask, accumulate row partials
#pragma unroll
        for (int ci = 0; ci < 4; ++ci) {
            int j   = c0 + tx * 4 + ci;
            float sqj = g_sq[j];
            int   lj  = lc[tx * 4 + ci];
#pragma unroll
            for (int ri = 0; ri < 4; ++ri) {
                if (myl[ri] != lj) {
                    float Dv = sqi[ri] + sqj - 2.f * acc[ri][ci];
                    rowacc[ri] += __expf(Dv);
                }
            }
        }
    }

    // deterministic cross-thread reduction per row
#pragma unroll
    for (int ri = 0; ri < 4; ++ri) red[ty * 4 + ri][tx] = rowacc[ri];
    __syncthreads();
    if (tid < BM) {
        float s = 0.f;
#pragma unroll
        for (int t = 0; t < 16; ++t) s += red[tid][t];
        g_Zpart[half][r0 + tid] = s;
    }
}

// ---------------- kernel E: per-class positive-pair loss ----------------
__global__ __launch_bounds__(256)
void pair_kernel(const float* __restrict__ emb) {
    const int c   = blockIdx.x;
    const int tid = threadIdx.x;
    const int m   = g_class_count[c];

    __shared__ float s_anchor[DIM];
    __shared__ float s_red[256];

    float local = 0.f;
    for (int p = 0; p < m - 1; ++p) {
        int i = g_class_members[c][p];
        __syncthreads();
        if (tid < DIM / 4) {
            reinterpret_cast<float4*>(s_anchor)[tid] =
                reinterpret_cast<const float4*>(emb + (size_t)i * DIM)[tid];
        }
        __syncthreads();
        float sqi = g_sq[i];
        float Zi  = g_Zpart[0][i] + g_Zpart[1][i];
        for (int q = p + 1 + tid; q < m; q += 256) {
            int j = g_class_members[c][q];
            const float4* xj = reinterpret_cast<const float4*>(emb + (size_t)j * DIM);
            float dot = 0.f;
#pragma unroll
            for (int t = 0; t < DIM / 4; ++t) {
                float4 a = reinterpret_cast<const float4*>(s_anchor)[t];
                float4 b = __ldg(&xj[t]);
                dot += a.x * b.x + a.y * b.y + a.z * b.z + a.w * b.w;
            }
            float Dv = sqi + g_sq[j] - 2.f * dot;
            local += log1pf(Zi * __expf(-Dv));
        }
    }

    s_red[tid] = local;
    __syncthreads();
    for (int s = 128; s > 0; s >>= 1) {
        if (tid < s) s_red[tid] += s_red[tid + s];
        __syncthreads();
    }
    if (tid == 0) {
        if (m >= 2) {
            float T = 0.5f * (float)m * (float)(m - 1);
            g_label_mean[c]  = s_red[0] / T;
            g_label_valid[c] = 1;
        } else {
            g_label_mean[c]  = 0.f;
            g_label_valid[c] = 0;
        }
    }
}

// ---------------- kernel F: final scalar ----------------
__global__ void final_kernel(float* __restrict__ out) {
    if (threadIdx.x == 0) {
        float s = 0.f;
        int nv = 0;
        for (int c = 0; c < NCLS; ++c) {
            if (g_label_valid[c]) { s += g_label_mean[c]; nv++; }
        }
        out[0] = s / (float)(nv > 0 ? nv : 1);
    }
}

// ---------------- launch ----------------
extern "C" void kernel_launch(void* const* d_in, const int* in_sizes, int n_in,
                              void* d_out, int out_size) {
    const float* emb    = (const float*)d_in[0];
    const int*   labels = (const int*)d_in[1];
    float*       out    = (float*)d_out;

    sq_kernel<<<(N + 255) / 256, 256>>>(emb);
    classes_kernel<<<NCLS, 32>>>(labels);
    z_kernel<<<dim3(N / BM, 2), 256>>>(emb, labels);
    pair_kernel<<<NCLS, 256>>>(emb);
    final_kernel<<<1, 32>>>(out);
}

// round 2
// speedup vs baseline: 2.1104x; 2.1104x over previous
#include <cuda_runtime.h>
#include <cuda_bf16.h>
#include <math.h>

#define N      8192
#define DIM    128
#define NCLS   64
#define BM     128
#define BN     128
#define KSPLIT 4
#define COLS_PER_SPLIT (N / KSPLIT)
#define TILES_PER_SPLIT (COLS_PER_SPLIT / BN)
#define MAXMEM 8192

// ---------------- scratch (device globals; no allocation) ----------------
__device__ float g_sq[N];
__device__ float g_Zpart[KSPLIT][N];
__device__ int   g_class_members[NCLS][MAXMEM];
__device__ int   g_class_count[NCLS];
__device__ float g_rowsum[N];
__device__ float g_label_mean[NCLS];
__device__ int   g_label_valid[NCLS];

// ---------------- kernel A: row squared norms ----------------
__global__ void sq_kernel(const float* __restrict__ emb) {
    int i = blockIdx.x * blockDim.x + threadIdx.x;
    if (i >= N) return;
    const float4* row = reinterpret_cast<const float4*>(emb + (size_t)i * DIM);
    float s = 0.f;
#pragma unroll
    for (int t = 0; t < DIM / 4; ++t) {
        float4 v = row[t];
        s += v.x * v.x + v.y * v.y + v.z * v.z + v.w * v.w;
    }
    g_sq[i] = s;
}

// ---------------- kernel B: per-class member lists (deterministic, ascending) --------
__global__ void classes_kernel(const int* __restrict__ labels) {
    int c = blockIdx.x;
    int lane = threadIdx.x;
    int cnt = 0;
    for (int base = 0; base < N; base += 32) {
        int l = labels[base + lane];
        bool mine = (l == c);
        unsigned mask = __ballot_sync(0xffffffffu, mine);
        if (mine) {
            int pos = cnt + __popc(mask & ((1u << lane) - 1u));
            g_class_members[c][pos] = base + lane;
        }
        cnt += __popc(mask);
    }
    if (lane == 0) g_class_count[c] = cnt;
}

// ---------------- kernel C: Z[i] via 128x128 tiles, f32x2 packed FMA ----------------
// dyn smem layout
struct ZSmem {
    float As[DIM][BM];      // 64 KB, k-major
    float Bs[DIM][BN];      // 64 KB, k-major
    float red[BM][17];      // 8.7 KB
    int   lc[BN];
};

__global__ __launch_bounds__(256, 1)
void z_kernel(const float* __restrict__ emb, const int* __restrict__ labels) {
    extern __shared__ char smem_raw[];
    ZSmem* sm = reinterpret_cast<ZSmem*>(smem_raw);

    const int r0   = blockIdx.x * BM;
    const int cbeg = blockIdx.y * COLS_PER_SPLIT;

    const int tid = threadIdx.x;
    const int tx  = tid & 15;   // 16 col groups of 8
    const int ty  = tid >> 4;   // 16 row groups of 8

    // ---- load A tile (128 rows x 128 dims), transposed, conflict-free ----
    // lanes of a warp span 32 consecutive rows with identical k-group -> STS banks distinct
    for (int s = tid; s < BM * (DIM / 4); s += 256) {
        int c4  = s >> 7;      // 0..31 : which float4 along dim
        int row = s & 127;     // 0..127
        float4 v = reinterpret_cast<const float4*>(emb + (size_t)(r0 + row) * DIM)[c4];
        int k = c4 * 4;
        sm->As[k + 0][row] = v.x;
        sm->As[k + 1][row] = v.y;
        sm->As[k + 2][row] = v.z;
        sm->As[k + 3][row] = v.w;
    }

    float sqi[8];
    int   myl[8];
    float rowacc[8];
#pragma unroll
    for (int ri = 0; ri < 8; ++ri) {
        int r = r0 + ty * 8 + ri;
        sqi[ri] = g_sq[r];
        myl[ri] = labels[r];
        rowacc[ri] = 0.f;
    }

    for (int tile = 0; tile < TILES_PER_SPLIT; ++tile) {
        const int c0 = cbeg + tile * BN;
        __syncthreads();   // previous tile compute done before Bs overwrite
        for (int s = tid; s < BN * (DIM / 4); s += 256) {
            int c4  = s >> 7;
            int row = s & 127;
            float4 v = reinterpret_cast<const float4*>(emb + (size_t)(c0 + row) * DIM)[c4];
            int k = c4 * 4;
            sm->Bs[k + 0][row] = v.x;
            sm->Bs[k + 1][row] = v.y;
            sm->Bs[k + 2][row] = v.z;
            sm->Bs[k + 3][row] = v.w;
        }
        if (tid < BN) sm->lc[tid] = labels[c0 + tid];
        __syncthreads();

        // acc2[rp][c] : packed pair of rows (2*rp, 2*rp+1) x column c
        unsigned long long acc2[4][8];
#pragma unroll
        for (int rp = 0; rp < 4; ++rp)
#pragma unroll
            for (int c = 0; c < 8; ++c) acc2[rp][c] = 0ull;

#pragma unroll 4
        for (int k = 0; k < DIM; ++k) {
            const ulonglong2* ap =
                reinterpret_cast<const ulonglong2*>(&sm->As[k][ty * 8]);
            ulonglong2 a01 = ap[0];
            ulonglong2 a23 = ap[1];
            unsigned long long arow[4] = {a01.x, a01.y, a23.x, a23.y};

            float4 b0 = *reinterpret_cast<const float4*>(&sm->Bs[k][tx * 8]);
            float4 b1 = *reinterpret_cast<const float4*>(&sm->Bs[k][tx * 8 + 4]);
            float bv[8] = {b0.x, b0.y, b0.z, b0.w, b1.x, b1.y, b1.z, b1.w};
            unsigned long long bb[8];
#pragma unroll
            for (int c = 0; c < 8; ++c)
                asm("mov.b64 %0, {%1, %1};" : "=l"(bb[c]) : "f"(bv[c]));

#pragma unroll
            for (int rp = 0; rp < 4; ++rp)
#pragma unroll
                for (int c = 0; c < 8; ++c)
                    asm("fma.rn.f32x2 %0, %1, %2, %0;"
                        : "+l"(acc2[rp][c]) : "l"(arow[rp]), "l"(bb[c]));
        }

        // epilogue: D = sqi + sqj - 2*dot; accumulate exp over negatives
#pragma unroll
        for (int c = 0; c < 8; ++c) {
            int j = c0 + tx * 8 + c;
            float sqj = g_sq[j];
            int   lj  = sm->lc[tx * 8 + c];
#pragma unroll
            for (int rp = 0; rp < 4; ++rp) {
                unsigned long long v = acc2[rp][c];
                float dlo = __uint_as_float((unsigned)(v & 0xffffffffu));
                float dhi = __uint_as_float((unsigned)(v >> 32));
                if (myl[2 * rp + 0] != lj)
                    rowacc[2 * rp + 0] += __expf(sqi[2 * rp + 0] + sqj - 2.f * dlo);
                if (myl[2 * rp + 1] != lj)
                    rowacc[2 * rp + 1] += __expf(sqi[2 * rp + 1] + sqj - 2.f * dhi);
            }
        }
    }

    // deterministic cross-thread row reduction
    __syncthreads();
#pragma unroll
    for (int ri = 0; ri < 8; ++ri) sm->red[ty * 8 + ri][tx] = rowacc[ri];
    __syncthreads();
    if (tid < BM) {
        float s = 0.f;
#pragma unroll
        for (int t = 0; t < 16; ++t) s += sm->red[tid][t];
        g_Zpart[blockIdx.y][r0 + tid] = s;
    }
}

// ---------------- kernel D: positive pairs, one warp per anchor ----------------
__global__ __launch_bounds__(256)
void pair_kernel(const float* __restrict__ emb, const int* __restrict__ labels) {
    const int warp = (blockIdx.x * blockDim.x + threadIdx.x) >> 5;   // anchor index
    const int lane = threadIdx.x & 31;
    if (warp >= N) return;
    const int a = warp;
    const int c = labels[a];
    const int m = g_class_count[c];

    float4 av = reinterpret_cast<const float4*>(emb + (size_t)a * DIM)[lane];
    float sqa = g_sq[a];
    float Za  = 0.f;
#pragma unroll
    for (int p = 0; p < KSPLIT; ++p) Za += g_Zpart[p][a];

    float lsum = 0.f;
    for (int q = 0; q < m; ++q) {
        int j = g_class_members[c][q];
        if (j <= a) continue;                 // uniform across warp
        float4 bv = reinterpret_cast<const float4*>(emb + (size_t)j * DIM)[lane];
        float d = av.x * bv.x + av.y * bv.y + av.z * bv.z + av.w * bv.w;
#pragma unroll
        for (int off = 16; off > 0; off >>= 1)
            d += __shfl_xor_sync(0xffffffffu, d, off);
        if (lane == 0) {
            float D = sqa + g_sq[j] - 2.f * d;
            lsum += log1pf(Za * __expf(-D));
        }
    }
    if (lane == 0) g_rowsum[a] = lsum;
}

// ---------------- kernel E: per-class mean (deterministic tree) ----------------
__global__ void mean_kernel() {
    const int c = blockIdx.x;
    const int lane = threadIdx.x;
    const int m = g_class_count[c];
    float s = 0.f;
    for (int q = lane; q < m; q += 32) s += g_rowsum[g_class_members[c][q]];
#pragma unroll
    for (int off = 16; off > 0; off >>= 1)
        s += __shfl_xor_sync(0xffffffffu, s, off);
    if (lane == 0) {
        if (m >= 2) {
            float T = 0.5f * (float)m * (float)(m - 1);
            g_label_mean[c]  = s / T;
            g_label_valid[c] = 1;
        } else {
            g_label_mean[c]  = 0.f;
            g_label_valid[c] = 0;
        }
    }
}

// ---------------- kernel F: final scalar ----------------
__global__ void final_kernel(float* __restrict__ out) {
    if (threadIdx.x == 0) {
        float s = 0.f;
        int nv = 0;
        for (int c = 0; c < NCLS; ++c) {
            if (g_label_valid[c]) { s += g_label_mean[c]; nv++; }
        }
        out[0] = s / (float)(nv > 0 ? nv : 1);
    }
}

// ---------------- launch ----------------
extern "C" void kernel_launch(void* const* d_in, const int* in_sizes, int n_in,
                              void* d_out, int out_size) {
    const float* emb    = (const float*)d_in[0];
    const int*   labels = (const int*)d_in[1];
    float*       out    = (float*)d_out;

    static bool attr_set = false;
    if (!attr_set) {
        cudaFuncSetAttribute(z_kernel,
                             cudaFuncAttributeMaxDynamicSharedMemorySize,
                             (int)sizeof(ZSmem));
        attr_set = true;
    }

    sq_kernel<<<(N + 255) / 256, 256>>>(emb);
    classes_kernel<<<NCLS, 32>>>(labels);
    z_kernel<<<dim3(N / BM, KSPLIT), 256, sizeof(ZSmem)>>>(emb, labels);
    pair_kernel<<<N / 8, 256>>>(emb, labels);
    mean_kernel<<<NCLS, 32>>>();
    final_kernel<<<1, 32>>>(out);
}

// round 4
// speedup vs baseline: 4.1977x; 1.9890x over previous
#include <cuda_runtime.h>
#include <cuda_bf16.h>
#include <math.h>
#include <stdint.h>

#define N      8192
#define DIM    128
#define NCLS   64
#define BM     128
#define BN     128
#define KSPLIT 4
#define COLS_PER_SPLIT (N / KSPLIT)
#define TILES_PER_SPLIT (COLS_PER_SPLIT / BN)
#define MAXMEM 8192

// bf16 tile pitch: 136 bf16 = 272 bytes (272 mod 128 = 16 -> 8 rows cover all banks)
#define PITCHB 272
#define TILE_BYTES (128 * PITCHB)   // 34816

#define OFF_SQS  0
#define OFF_LC   512
#define OFF_RED  1024                 // 128 x 17 floats = 8704 B
#define OFF_AHI  9728
#define OFF_ALO  (OFF_AHI + TILE_BYTES)
#define OFF_BHI  (OFF_ALO + TILE_BYTES)
#define OFF_BLO  (OFF_BHI + TILE_BYTES)
#define Z_SMEM   (OFF_BLO + TILE_BYTES)   // 148992

// ---------------- helpers ----------------
__device__ __forceinline__ uint32_t smem_u32(const void* p) {
    uint32_t a;
    asm("{ .reg .u64 t; cvta.to.shared.u64 t, %1; cvt.u32.u64 %0, t; }" : "=r"(a) : "l"(p));
    return a;
}

#define LDSM4(r, addr) \
    asm volatile("ldmatrix.sync.aligned.m8n8.x4.shared.b16 {%0,%1,%2,%3}, [%4];" \
        : "=r"((r)[0]), "=r"((r)[1]), "=r"((r)[2]), "=r"((r)[3]) : "r"(addr))

__device__ __forceinline__ void mma16816(float* c, const uint32_t* a,
                                         uint32_t b0, uint32_t b1) {
    asm volatile(
        "mma.sync.aligned.m16n8k16.row.col.f32.bf16.bf16.f32 "
        "{%0,%1,%2,%3}, {%4,%5,%6,%7}, {%8,%9}, {%0,%1,%2,%3};"
        : "+f"(c[0]), "+f"(c[1]), "+f"(c[2]), "+f"(c[3])
        : "r"(a[0]), "r"(a[1]), "r"(a[2]), "r"(a[3]), "r"(b0), "r"(b1));
}

// split f32 row chunk of 8 into bf16 hi/lo, store 16B each
__device__ __forceinline__ void cvt_store8(char* base_hi, char* base_lo,
                                           uint32_t off, const float* xs) {
    uint32_t hw[4], lw[4];
#pragma unroll
    for (int p = 0; p < 4; ++p) {
        float x0 = xs[2 * p], x1 = xs[2 * p + 1];
        __nv_bfloat16 h0 = __float2bfloat16_rn(x0);
        __nv_bfloat16 h1 = __float2bfloat16_rn(x1);
        __nv_bfloat16 l0 = __float2bfloat16_rn(x0 - __bfloat162float(h0));
        __nv_bfloat16 l1 = __float2bfloat16_rn(x1 - __bfloat162float(h1));
        hw[p] = (uint32_t)__bfloat16_as_ushort(h0) | ((uint32_t)__bfloat16_as_ushort(h1) << 16);
        lw[p] = (uint32_t)__bfloat16_as_ushort(l0) | ((uint32_t)__bfloat16_as_ushort(l1) << 16);
    }
    *reinterpret_cast<uint4*>(base_hi + off) = make_uint4(hw[0], hw[1], hw[2], hw[3]);
    *reinterpret_cast<uint4*>(base_lo + off) = make_uint4(lw[0], lw[1], lw[2], lw[3]);
}

// ---------------- scratch ----------------
__device__ float g_sq[N];
__device__ float g_Zpart[KSPLIT][N];
__device__ int   g_class_members[NCLS][MAXMEM];
__device__ int   g_class_count[NCLS];
__device__ float g_rowsum[N];
__device__ float g_label_mean[NCLS];
__device__ int   g_label_valid[NCLS];

// ---------------- kernel A: row squared norms ----------------
__global__ void sq_kernel(const float* __restrict__ emb) {
    int i = blockIdx.x * blockDim.x + threadIdx.x;
    if (i >= N) return;
    const float4* row = reinterpret_cast<const float4*>(emb + (size_t)i * DIM);
    float s = 0.f;
#pragma unroll
    for (int t = 0; t < DIM / 4; ++t) {
        float4 v = row[t];
        s += v.x * v.x + v.y * v.y + v.z * v.z + v.w * v.w;
    }
    g_sq[i] = s;
}

// ---------------- kernel B: per-class member lists ----------------
__global__ void classes_kernel(const int* __restrict__ labels) {
    int c = blockIdx.x, lane = threadIdx.x, cnt = 0;
    for (int base = 0; base < N; base += 32) {
        int l = labels[base + lane];
        bool mine = (l == c);
        unsigned mask = __ballot_sync(0xffffffffu, mine);
        if (mine) g_class_members[c][cnt + __popc(mask & ((1u << lane) - 1u))] = base + lane;
        cnt += __popc(mask);
    }
    if (lane == 0) g_class_count[c] = cnt;
}

// ---------------- z kernel: bf16-split mma.sync GEMM + fused exp epilogue --------
__global__ __launch_bounds__(256, 1)
void z_kernel(const float* __restrict__ emb, const int* __restrict__ labels) {
    extern __shared__ char sm[];
    float* sqs = reinterpret_cast<float*>(sm + OFF_SQS);
    int*   lc  = reinterpret_cast<int*>(sm + OFF_LC);
    float* red = reinterpret_cast<float*>(sm + OFF_RED);   // [128][17]
    const uint32_t smb = smem_u32(sm);

    const int tid  = threadIdx.x;
    const int wid  = tid >> 5;
    const int lane = tid & 31;
    const int warp_m = wid & 1;       // 2 row-halves of 64
    const int warp_n = wid >> 1;      // 4 col-quarters of 32
    const int g = lane >> 2;
    const int t = lane & 3;

    const int r0   = blockIdx.x * BM;
    const int cbeg = blockIdx.y * COLS_PER_SPLIT;

    // ---- load + split A tile (once) ----
    for (int s = tid; s < BM * 16; s += 256) {
        int row = s >> 4, k0 = (s & 15) * 8;
        const float4* src = reinterpret_cast<const float4*>(emb + (size_t)(r0 + row) * DIM + k0);
        float4 v0 = src[0], v1 = src[1];
        float xs[8] = {v0.x, v0.y, v0.z, v0.w, v1.x, v1.y, v1.z, v1.w};
        cvt_store8(sm + OFF_AHI, sm + OFF_ALO, (uint32_t)(row * PITCHB + k0 * 2), xs);
    }

    // ldmatrix per-lane base addresses
    const int mtx = lane >> 3, lrow = lane & 7;
    const uint32_t aoff = (uint32_t)((warp_m * 64 + (mtx & 1) * 8 + lrow) * PITCHB
                                     + ((mtx >> 1) * 8) * 2);
    const uint32_t boff = (uint32_t)((warp_n * 32 + (mtx >> 1) * 8 + lrow) * PITCHB
                                     + ((mtx & 1) * 8) * 2);
    const uint32_t aAhi = smb + OFF_AHI + aoff;
    const uint32_t aAlo = smb + OFF_ALO + aoff;
    const uint32_t aBhi = smb + OFF_BHI + boff;
    const uint32_t aBlo = smb + OFF_BLO + boff;

    // per-thread row identity (8 rows)
    float sqi[8]; int myl[8]; float rowacc[8];
#pragma unroll
    for (int am = 0; am < 4; ++am)
#pragma unroll
        for (int h = 0; h < 2; ++h) {
            int r = r0 + warp_m * 64 + am * 16 + h * 8 + g;
            sqi[am * 2 + h] = g_sq[r];
            myl[am * 2 + h] = labels[r];
            rowacc[am * 2 + h] = 0.f;
        }

    for (int tile = 0; tile < TILES_PER_SPLIT; ++tile) {
        const int c0 = cbeg + tile * BN;
        __syncthreads();   // prior compute done (and A-convert on tile 0)

        // ---- load + split B tile ----
        for (int s = tid; s < BN * 16; s += 256) {
            int row = s >> 4, k0 = (s & 15) * 8;
            const float4* src = reinterpret_cast<const float4*>(emb + (size_t)(c0 + row) * DIM + k0);
            float4 v0 = src[0], v1 = src[1];
            float xs[8] = {v0.x, v0.y, v0.z, v0.w, v1.x, v1.y, v1.z, v1.w};
            cvt_store8(sm + OFF_BHI, sm + OFF_BLO, (uint32_t)(row * PITCHB + k0 * 2), xs);
        }
        if (tid < BN) {
            sqs[tid] = g_sq[c0 + tid];
            lc[tid]  = labels[c0 + tid];
        }
        __syncthreads();

        // ---- mainloop: 3-pass bf16-split MMA ----
        float acc[16][4];
#pragma unroll
        for (int i = 0; i < 16; ++i)
#pragma unroll
            for (int j = 0; j < 4; ++j) acc[i][j] = 0.f;

#pragma unroll
        for (int ks = 0; ks < 8; ++ks) {
            const uint32_t kb = (uint32_t)ks * 32;   // 16 bf16 = 32 bytes
            uint32_t ah[4][4], al[4][4], bh[2][4], bl[2][4];
#pragma unroll
            for (int am = 0; am < 4; ++am) {
                LDSM4(ah[am], aAhi + (uint32_t)am * (16 * PITCHB) + kb);
                LDSM4(al[am], aAlo + (uint32_t)am * (16 * PITCHB) + kb);
            }
#pragma unroll
            for (int bn = 0; bn < 2; ++bn) {
                LDSM4(bh[bn], aBhi + (uint32_t)bn * (16 * PITCHB) + kb);
                LDSM4(bl[bn], aBlo + (uint32_t)bn * (16 * PITCHB) + kb);
            }
#pragma unroll
            for (int am = 0; am < 4; ++am)
#pragma unroll
                for (int na = 0; na < 4; ++na) {
                    const int bn = na >> 1, p = (na & 1) * 2;
                    mma16816(acc[am * 4 + na], ah[am], bh[bn][p], bh[bn][p + 1]);
                    mma16816(acc[am * 4 + na], ah[am], bl[bn][p], bl[bn][p + 1]);
                    mma16816(acc[am * 4 + na], al[am], bh[bn][p], bh[bn][p + 1]);
                }
        }

        // ---- fused epilogue: D + masked exp ----
#pragma unroll
        for (int am = 0; am < 4; ++am)
#pragma unroll
            for (int na = 0; na < 4; ++na) {
                const int nn0 = warp_n * 32 + na * 8 + 2 * t;
#pragma unroll
                for (int h = 0; h < 2; ++h)
#pragma unroll
                    for (int cc = 0; cc < 2; ++cc) {
                        float dot = acc[am * 4 + na][h * 2 + cc];
                        int nj = nn0 + cc;
                        float D = fmaf(-2.f, dot, sqi[am * 2 + h] + sqs[nj]);
                        if (myl[am * 2 + h] != lc[nj])
                            rowacc[am * 2 + h] += __expf(D);
                    }
            }
    }

    // ---- deterministic row reduction ----
    __syncthreads();
#pragma unroll
    for (int am = 0; am < 4; ++am)
#pragma unroll
        for (int h = 0; h < 2; ++h) {
            int mloc = warp_m * 64 + am * 16 + h * 8 + g;
            red[mloc * 17 + warp_n * 4 + t] = rowacc[am * 2 + h];
        }
    __syncthreads();
    if (tid < BM) {
        float s = 0.f;
#pragma unroll
        for (int q = 0; q < 16; ++q) s += red[tid * 17 + q];
        g_Zpart[blockIdx.y][r0 + tid] = s;
    }
}

// ---------------- pair kernel: warp per anchor, lane per candidate ----------------
__global__ __launch_bounds__(256)
void pair_kernel(const float* __restrict__ emb, const int* __restrict__ labels) {
    __shared__ float prow[8][DIM];
    const int w    = threadIdx.x >> 5;
    const int lane = threadIdx.x & 31;
    const int a    = blockIdx.x * 8 + w;

    reinterpret_cast<float4*>(prow[w])[lane] =
        reinterpret_cast<const float4*>(emb + (size_t)a * DIM)[lane];
    __syncwarp();

    const int c = labels[a];
    const int m = g_class_count[c];
    const float sqa = g_sq[a];
    float Za = 0.f;
#pragma unroll
    for (int p = 0; p < KSPLIT; ++p) Za += g_Zpart[p][a];

    float lsum = 0.f;
    for (int q0 = 0; q0 < m; q0 += 32) {
        int qi = q0 + lane;
        int j = (qi < m) ? g_class_members[c][qi] : -1;
        if (j > a) {
            const float4* bj = reinterpret_cast<const float4*>(emb + (size_t)j * DIM);
            float d = 0.f;
#pragma unroll
            for (int k = 0; k < DIM / 4; ++k) {
                float4 av = reinterpret_cast<const float4*>(prow[w])[k];
                float4 bv = __ldg(&bj[k]);
                d += av.x * bv.x + av.y * bv.y + av.z * bv.z + av.w * bv.w;
            }
            float D = sqa + g_sq[j] - 2.f * d;
            lsum += log1pf(Za * __expf(-D));
        }
    }
#pragma unroll
    for (int off = 16; off > 0; off >>= 1)
        lsum += __shfl_xor_sync(0xffffffffu, lsum, off);
    if (lane == 0) g_rowsum[a] = lsum;
}

// ---------------- mean + final ----------------
__global__ void mean_kernel() {
    const int c = blockIdx.x, lane = threadIdx.x;
    const int m = g_class_count[c];
    float s = 0.f;
    for (int q = lane; q < m; q += 32) s += g_rowsum[g_class_members[c][q]];
#pragma unroll
    for (int off = 16; off > 0; off >>= 1) s += __shfl_xor_sync(0xffffffffu, s, off);
    if (lane == 0) {
        if (m >= 2) {
            float T = 0.5f * (float)m * (float)(m - 1);
            g_label_mean[c] = s / T;
            g_label_valid[c] = 1;
        } else { g_label_mean[c] = 0.f; g_label_valid[c] = 0; }
    }
}

__global__ void final_kernel(float* __restrict__ out) {
    if (threadIdx.x == 0) {
        float s = 0.f; int nv = 0;
        for (int c = 0; c < NCLS; ++c)
            if (g_label_valid[c]) { s += g_label_mean[c]; nv++; }
        out[0] = s / (float)(nv > 0 ? nv : 1);
    }
}

// ---------------- launch ----------------
extern "C" void kernel_launch(void* const* d_in, const int* in_sizes, int n_in,
                              void* d_out, int out_size) {
    const float* emb    = (const float*)d_in[0];
    const int*   labels = (const int*)d_in[1];
    float*       out    = (float*)d_out;

    static bool attr_set = false;
    if (!attr_set) {
        cudaFuncSetAttribute(z_kernel, cudaFuncAttributeMaxDynamicSharedMemorySize, Z_SMEM);
        attr_set = true;
    }

    sq_kernel<<<(N + 255) / 256, 256>>>(emb);
    classes_kernel<<<NCLS, 32>>>(labels);
    z_kernel<<<dim3(N / BM, KSPLIT), 256, Z_SMEM>>>(emb, labels);
    pair_kernel<<<N / 8, 256>>>(emb, labels);
    mean_kernel<<<NCLS, 32>>>();
    final_kernel<<<1, 32>>>(out);
}

// round 5
// speedup vs baseline: 5.2722x; 1.2560x over previous
#include <cuda_runtime.h>
#include <cuda_bf16.h>
#include <math.h>
#include <stdint.h>

#define N      8192
#define DIM    128
#define NCLS   64
#define BM     128
#define BN     128
#define KSPLIT 4
#define COLS_PER_SPLIT (N / KSPLIT)
#define TILES_PER_SPLIT (COLS_PER_SPLIT / BN)
#define MAXMEM 8192
#define MAXM   256          // max members per class (mean 128, +11 sigma safe)
#define L2E    1.4426950408889634f

// bf16 tile pitch: 136 bf16 = 272 bytes (272 mod 128 = 16 -> conflict-free ldmatrix)
#define PITCHB 272
#define TILE_BYTES (128 * PITCHB)   // 34816

#define OFF_RLAB 0
#define OFF_RCI  512
#define OFF_CJ   1024
#define OFF_LC   1536
#define OFF_AHI  2048
#define OFF_BHI  (OFF_AHI + TILE_BYTES)
#define OFF_BLO  (OFF_BHI + TILE_BYTES)
#define Z_SMEM   (OFF_BLO + TILE_BYTES)   // 106496 -> occ 2

// ---------------- helpers ----------------
__device__ __forceinline__ uint32_t smem_u32(const void* p) {
    uint32_t a;
    asm("{ .reg .u64 t; cvta.to.shared.u64 t, %1; cvt.u32.u64 %0, t; }" : "=r"(a) : "l"(p));
    return a;
}
__device__ __forceinline__ float ex2(float x) {
    float y;
    asm("ex2.approx.ftz.f32 %0, %1;" : "=f"(y) : "f"(x));
    return y;
}

#define LDSM4(r, addr) \
    asm volatile("ldmatrix.sync.aligned.m8n8.x4.shared.b16 {%0,%1,%2,%3}, [%4];" \
        : "=r"((r)[0]), "=r"((r)[1]), "=r"((r)[2]), "=r"((r)[3]) : "r"(addr))

__device__ __forceinline__ void mma16816(float* c, const uint32_t* a,
                                         uint32_t b0, uint32_t b1) {
    asm volatile(
        "mma.sync.aligned.m16n8k16.row.col.f32.bf16.bf16.f32 "
        "{%0,%1,%2,%3}, {%4,%5,%6,%7}, {%8,%9}, {%0,%1,%2,%3};"
        : "+f"(c[0]), "+f"(c[1]), "+f"(c[2]), "+f"(c[3])
        : "r"(a[0]), "r"(a[1]), "r"(a[2]), "r"(a[3]), "r"(b0), "r"(b1));
}

// A: single bf16 (pre-scaled), 8 values -> 16B
__device__ __forceinline__ void storeA8(char* base, uint32_t off, const float* xs) {
    uint32_t w[4];
#pragma unroll
    for (int p = 0; p < 4; ++p) {
        __nv_bfloat16 h0 = __float2bfloat16_rn(xs[2 * p]);
        __nv_bfloat16 h1 = __float2bfloat16_rn(xs[2 * p + 1]);
        w[p] = (uint32_t)__bfloat16_as_ushort(h0) | ((uint32_t)__bfloat16_as_ushort(h1) << 16);
    }
    *reinterpret_cast<uint4*>(base + off) = make_uint4(w[0], w[1], w[2], w[3]);
}
// B: hi/lo split
__device__ __forceinline__ void storeB8(char* bhi, char* blo, uint32_t off, const float* xs) {
    uint32_t hw[4], lw[4];
#pragma unroll
    for (int p = 0; p < 4; ++p) {
        float x0 = xs[2 * p], x1 = xs[2 * p + 1];
        __nv_bfloat16 h0 = __float2bfloat16_rn(x0);
        __nv_bfloat16 h1 = __float2bfloat16_rn(x1);
        __nv_bfloat16 l0 = __float2bfloat16_rn(x0 - __bfloat162float(h0));
        __nv_bfloat16 l1 = __float2bfloat16_rn(x1 - __bfloat162float(h1));
        hw[p] = (uint32_t)__bfloat16_as_ushort(h0) | ((uint32_t)__bfloat16_as_ushort(h1) << 16);
        lw[p] = (uint32_t)__bfloat16_as_ushort(l0) | ((uint32_t)__bfloat16_as_ushort(l1) << 16);
    }
    *reinterpret_cast<uint4*>(bhi + off) = make_uint4(hw[0], hw[1], hw[2], hw[3]);
    *reinterpret_cast<uint4*>(blo + off) = make_uint4(lw[0], lw[1], lw[2], lw[3]);
}

// ---------------- scratch ----------------
__device__ float g_sq[N];
__device__ float g_csq[N];                      // L2E * sq
__device__ float g_Zpart[KSPLIT][N];
__device__ int   g_class_members[NCLS][MAXMEM];
__device__ int   g_class_count[NCLS];
__device__ int   g_rank[N];
__device__ float g_Dpair[NCLS][MAXM][MAXM];     // exp(-D) for same-class i<j
__device__ float g_label_mean[NCLS];
__device__ int   g_label_valid[NCLS];

// ---------------- kernel A: norms ----------------
__global__ void sq_kernel(const float* __restrict__ emb) {
    int i = blockIdx.x * blockDim.x + threadIdx.x;
    if (i >= N) return;
    const float4* row = reinterpret_cast<const float4*>(emb + (size_t)i * DIM);
    float s = 0.f;
#pragma unroll
    for (int t = 0; t < DIM / 4; ++t) {
        float4 v = row[t];
        s += v.x * v.x + v.y * v.y + v.z * v.z + v.w * v.w;
    }
    g_sq[i]  = s;
    g_csq[i] = s * L2E;
}

// ---------------- kernel B: member lists + ranks ----------------
__global__ void classes_kernel(const int* __restrict__ labels) {
    int c = blockIdx.x, lane = threadIdx.x, cnt = 0;
    for (int base = 0; base < N; base += 32) {
        int l = labels[base + lane];
        bool mine = (l == c);
        unsigned mask = __ballot_sync(0xffffffffu, mine);
        if (mine) {
            int pos = cnt + __popc(mask & ((1u << lane) - 1u));
            g_class_members[c][pos] = base + lane;
            g_rank[base + lane] = pos;
        }
        cnt += __popc(mask);
    }
    if (lane == 0) g_class_count[c] = cnt;
}

// ---------------- z kernel ----------------
__global__ __launch_bounds__(256, 2)
void z_kernel(const float* __restrict__ emb, const int* __restrict__ labels) {
    extern __shared__ char sm[];
    int*   rlab = reinterpret_cast<int*>(sm + OFF_RLAB);
    float* rci  = reinterpret_cast<float*>(sm + OFF_RCI);
    float* cjs  = reinterpret_cast<float*>(sm + OFF_CJ);
    int*   lc   = reinterpret_cast<int*>(sm + OFF_LC);
    const uint32_t smb = smem_u32(sm);

    const int tid  = threadIdx.x;
    const int wid  = tid >> 5;
    const int lane = tid & 31;
    const int warp_m = wid & 1;
    const int warp_n = wid >> 1;
    const int g = lane >> 2;
    const int t = lane & 3;

    const int r0   = blockIdx.x * BM;
    const int cbeg = blockIdx.y * COLS_PER_SPLIT;
    const float ASCALE = -2.f * L2E;

    // A tile: scaled bf16 (hi only)
    for (int s = tid; s < BM * 16; s += 256) {
        int row = s >> 4, k0 = (s & 15) * 8;
        const float4* src = reinterpret_cast<const float4*>(emb + (size_t)(r0 + row) * DIM + k0);
        float4 v0 = src[0], v1 = src[1];
        float xs[8] = {v0.x * ASCALE, v0.y * ASCALE, v0.z * ASCALE, v0.w * ASCALE,
                       v1.x * ASCALE, v1.y * ASCALE, v1.z * ASCALE, v1.w * ASCALE};
        storeA8(sm + OFF_AHI, (uint32_t)(row * PITCHB + k0 * 2), xs);
    }
    if (tid < BM) {
        rlab[tid] = labels[r0 + tid];
        rci[tid]  = g_csq[r0 + tid];
    }

    const int mtx = lane >> 3, lrow = lane & 7;
    const uint32_t aoff = (uint32_t)((warp_m * 64 + (mtx & 1) * 8 + lrow) * PITCHB
                                     + ((mtx >> 1) * 8) * 2);
    const uint32_t boff = (uint32_t)((warp_n * 32 + (mtx >> 1) * 8 + lrow) * PITCHB
                                     + ((mtx & 1) * 8) * 2);
    const uint32_t aAhi = smb + OFF_AHI + aoff;
    const uint32_t aBhi = smb + OFF_BHI + boff;
    const uint32_t aBlo = smb + OFF_BLO + boff;

    int myl[8];
    float rowacc[8];
#pragma unroll
    for (int rr = 0; rr < 8; ++rr) rowacc[rr] = 0.f;

    for (int tile = 0; tile < TILES_PER_SPLIT; ++tile) {
        const int c0 = cbeg + tile * BN;
        __syncthreads();

        for (int s = tid; s < BN * 16; s += 256) {
            int row = s >> 4, k0 = (s & 15) * 8;
            const float4* src = reinterpret_cast<const float4*>(emb + (size_t)(c0 + row) * DIM + k0);
            float4 v0 = src[0], v1 = src[1];
            float xs[8] = {v0.x, v0.y, v0.z, v0.w, v1.x, v1.y, v1.z, v1.w};
            storeB8(sm + OFF_BHI, sm + OFF_BLO, (uint32_t)(row * PITCHB + k0 * 2), xs);
        }
        if (tid < BN) {
            cjs[tid] = g_csq[c0 + tid];
            lc[tid]  = labels[c0 + tid];
        }
        __syncthreads();

        float acc[16][4];
#pragma unroll
        for (int i = 0; i < 16; ++i)
#pragma unroll
            for (int j = 0; j < 4; ++j) acc[i][j] = 0.f;

#pragma unroll
        for (int ks = 0; ks < 8; ++ks) {
            const uint32_t kb = (uint32_t)ks * 32;
            uint32_t ah[4][4], bh[2][4], bl[2][4];
#pragma unroll
            for (int am = 0; am < 4; ++am)
                LDSM4(ah[am], aAhi + (uint32_t)am * (16 * PITCHB) + kb);
#pragma unroll
            for (int bn = 0; bn < 2; ++bn) {
                LDSM4(bh[bn], aBhi + (uint32_t)bn * (16 * PITCHB) + kb);
                LDSM4(bl[bn], aBlo + (uint32_t)bn * (16 * PITCHB) + kb);
            }
#pragma unroll
            for (int am = 0; am < 4; ++am)
#pragma unroll
                for (int na = 0; na < 4; ++na) {
                    const int bn = na >> 1, p = (na & 1) * 2;
                    mma16816(acc[am * 4 + na], ah[am], bh[bn][p], bh[bn][p + 1]);
                    mma16816(acc[am * 4 + na], ah[am], bl[bn][p], bl[bn][p + 1]);
                }
        }

        // epilogue: s = -2*L2E*dot ; exp(D) = 2^(ci + cj + s)
        float cjv[8]; int ljv[8];
#pragma unroll
        for (int na = 0; na < 4; ++na)
#pragma unroll
            for (int cc = 0; cc < 2; ++cc) {
                int idx = na * 2 + cc;
                int nj = warp_n * 32 + na * 8 + 2 * t + cc;
                cjv[idx] = cjs[nj];
                ljv[idx] = lc[nj];
            }
#pragma unroll
        for (int am = 0; am < 4; ++am)
#pragma unroll
            for (int h = 0; h < 2; ++h) {
                const int rr = am * 2 + h;
                const int mloc = warp_m * 64 + am * 16 + h * 8 + g;
                if (tile == 0) myl[rr] = rlab[mloc];
                const int ml = myl[rr];
                float racc = rowacc[rr];
#pragma unroll
                for (int na = 0; na < 4; ++na)
#pragma unroll
                    for (int cc = 0; cc < 2; ++cc) {
                        const int idx = na * 2 + cc;
                        float tv = acc[am * 4 + na][h * 2 + cc] + cjv[idx];
                        if (ml != ljv[idx]) {
                            racc += ex2(tv);
                        } else {
                            int gi = r0 + mloc;
                            int gj = c0 + warp_n * 32 + na * 8 + 2 * t + cc;
                            if (gj > gi) {
                                float e = ex2(-(tv + rci[mloc]));
                                g_Dpair[ml][g_rank[gi]][g_rank[gj]] = e;
                            }
                        }
                    }
                rowacc[rr] = racc;
            }
    }

    // row reduction (reuse Bhi region)
    __syncthreads();
    float* red = reinterpret_cast<float*>(sm + OFF_BHI);   // [128][17]
#pragma unroll
    for (int am = 0; am < 4; ++am)
#pragma unroll
        for (int h = 0; h < 2; ++h) {
            int mloc = warp_m * 64 + am * 16 + h * 8 + g;
            red[mloc * 17 + warp_n * 4 + t] = rowacc[am * 2 + h];
        }
    __syncthreads();
    if (tid < BM) {
        float s = 0.f;
#pragma unroll
        for (int q = 0; q < 16; ++q) s += red[tid * 17 + q];
        g_Zpart[blockIdx.y][r0 + tid] = s * ex2(rci[tid]);
    }
}

// ---------------- pair kernel: pure table lookups ----------------
__global__ __launch_bounds__(256)
void pair2_kernel() {
    __shared__ float s_red[256];
    const int c   = blockIdx.x;
    const int tid = threadIdx.x;
    const int m   = g_class_count[c];

    float lsum = 0.f;
    for (int p = 0; p < m - 1; ++p) {
        int i = g_class_members[c][p];
        float Za = g_Zpart[0][i] + g_Zpart[1][i] + g_Zpart[2][i] + g_Zpart[3][i];
        for (int q = p + 1 + tid; q < m; q += 256)
            lsum += log1pf(Za * g_Dpair[c][p][q]);
    }
    s_red[tid] = lsum;
    __syncthreads();
    for (int s = 128; s > 0; s >>= 1) {
        if (tid < s) s_red[tid] += s_red[tid + s];
        __syncthreads();
    }
    if (tid == 0) {
        if (m >= 2) {
            float T = 0.5f * (float)m * (float)(m - 1);
            g_label_mean[c]  = s_red[0] / T;
            g_label_valid[c] = 1;
        } else {
            g_label_mean[c]  = 0.f;
            g_label_valid[c] = 0;
        }
    }
}

__global__ void final_kernel(float* __restrict__ out) {
    if (threadIdx.x == 0) {
        float s = 0.f; int nv = 0;
        for (int c = 0; c < NCLS; ++c)
            if (g_label_valid[c]) { s += g_label_mean[c]; nv++; }
        out[0] = s / (float)(nv > 0 ? nv : 1);
    }
}

// ---------------- launch ----------------
extern "C" void kernel_launch(void* const* d_in, const int* in_sizes, int n_in,
                              void* d_out, int out_size) {
    const float* emb    = (const float*)d_in[0];
    const int*   labels = (const int*)d_in[1];
    float*       out    = (float*)d_out;

    static bool attr_set = false;
    if (!attr_set) {
        cudaFuncSetAttribute(z_kernel, cudaFuncAttributeMaxDynamicSharedMemorySize, Z_SMEM);
        attr_set = true;
    }

    sq_kernel<<<(N + 255) / 256, 256>>>(emb);
    classes_kernel<<<NCLS, 32>>>(labels);
    z_kernel<<<dim3(N / BM, KSPLIT), 256, Z_SMEM>>>(emb, labels);
    pair2_kernel<<<NCLS, 256>>>();
    final_kernel<<<1, 32>>>(out);
}

// round 6
// speedup vs baseline: 6.8697x; 1.3030x over previous
#include <cuda_runtime.h>
#include <cuda_bf16.h>
#include <math.h>
#include <stdint.h>

#define N      8192
#define DIM    128
#define NCLS   64
#define BM     128
#define BN     128
#define KSPLIT 4
#define COLS_PER_SPLIT (N / KSPLIT)
#define TILES_PER_SPLIT (COLS_PER_SPLIT / BN)
#define MAXMEM 8192
#define MAXM   256
#define L2E    1.4426950408889634f

#define PITCHB 272
#define TILE_BYTES (128 * PITCHB)

#define OFF_RLAB 0
#define OFF_RCI  512
#define OFF_CJ   1024
#define OFF_LC   1536
#define OFF_AHI  2048
#define OFF_BHI  (OFF_AHI + TILE_BYTES)
#define OFF_BLO  (OFF_BHI + TILE_BYTES)
#define Z_SMEM   (OFF_BLO + TILE_BYTES)   // 106496 -> occ 2

// ---------------- helpers ----------------
__device__ __forceinline__ uint32_t smem_u32(const void* p) {
    uint32_t a;
    asm("{ .reg .u64 t; cvta.to.shared.u64 t, %1; cvt.u32.u64 %0, t; }" : "=r"(a) : "l"(p));
    return a;
}
__device__ __forceinline__ float ex2(float x) {
    float y;
    asm("ex2.approx.ftz.f32 %0, %1;" : "=f"(y) : "f"(x));
    return y;
}

#define LDSM4(r, addr) \
    asm volatile("ldmatrix.sync.aligned.m8n8.x4.shared.b16 {%0,%1,%2,%3}, [%4];" \
        : "=r"((r)[0]), "=r"((r)[1]), "=r"((r)[2]), "=r"((r)[3]) : "r"(addr))

__device__ __forceinline__ void mma16816(float* c, const uint32_t* a,
                                         uint32_t b0, uint32_t b1) {
    asm volatile(
        "mma.sync.aligned.m16n8k16.row.col.f32.bf16.bf16.f32 "
        "{%0,%1,%2,%3}, {%4,%5,%6,%7}, {%8,%9}, {%0,%1,%2,%3};"
        : "+f"(c[0]), "+f"(c[1]), "+f"(c[2]), "+f"(c[3])
        : "r"(a[0]), "r"(a[1]), "r"(a[2]), "r"(a[3]), "r"(b0), "r"(b1));
}

__device__ __forceinline__ void storeA8(char* base, uint32_t off, const float* xs) {
    uint32_t w[4];
#pragma unroll
    for (int p = 0; p < 4; ++p) {
        __nv_bfloat16 h0 = __float2bfloat16_rn(xs[2 * p]);
        __nv_bfloat16 h1 = __float2bfloat16_rn(xs[2 * p + 1]);
        w[p] = (uint32_t)__bfloat16_as_ushort(h0) | ((uint32_t)__bfloat16_as_ushort(h1) << 16);
    }
    *reinterpret_cast<uint4*>(base + off) = make_uint4(w[0], w[1], w[2], w[3]);
}
__device__ __forceinline__ void storeB8(char* bhi, char* blo, uint32_t off, const float* xs) {
    uint32_t hw[4], lw[4];
#pragma unroll
    for (int p = 0; p < 4; ++p) {
        float x0 = xs[2 * p], x1 = xs[2 * p + 1];
        __nv_bfloat16 h0 = __float2bfloat16_rn(x0);
        __nv_bfloat16 h1 = __float2bfloat16_rn(x1);
        __nv_bfloat16 l0 = __float2bfloat16_rn(x0 - __bfloat162float(h0));
        __nv_bfloat16 l1 = __float2bfloat16_rn(x1 - __bfloat162float(h1));
        hw[p] = (uint32_t)__bfloat16_as_ushort(h0) | ((uint32_t)__bfloat16_as_ushort(h1) << 16);
        lw[p] = (uint32_t)__bfloat16_as_ushort(l0) | ((uint32_t)__bfloat16_as_ushort(l1) << 16);
    }
    *reinterpret_cast<uint4*>(bhi + off) = make_uint4(hw[0], hw[1], hw[2], hw[3]);
    *reinterpret_cast<uint4*>(blo + off) = make_uint4(lw[0], lw[1], lw[2], lw[3]);
}

// ---------------- scratch ----------------
__device__ float g_sq[N];
__device__ float g_csq[N];
__device__ float g_Zpart[KSPLIT][N];
__device__ int   g_class_members[NCLS][MAXMEM];
__device__ int   g_class_count[NCLS];
__device__ int   g_rank[N];
__device__ float g_Dpair[NCLS][MAXM][MAXM];
__device__ float g_rowsum[N];
__device__ float g_label_mean[NCLS];
__device__ int   g_label_valid[NCLS];

// ---------------- kernel A: norms ----------------
__global__ void sq_kernel(const float* __restrict__ emb) {
    int i = blockIdx.x * blockDim.x + threadIdx.x;
    if (i >= N) return;
    const float4* row = reinterpret_cast<const float4*>(emb + (size_t)i * DIM);
    float s = 0.f;
#pragma unroll
    for (int t = 0; t < DIM / 4; ++t) {
        float4 v = row[t];
        s += v.x * v.x + v.y * v.y + v.z * v.z + v.w * v.w;
    }
    g_sq[i]  = s;
    g_csq[i] = s * L2E;
}

// ---------------- kernel B: member lists + ranks ----------------
__global__ void classes_kernel(const int* __restrict__ labels) {
    int c = blockIdx.x, lane = threadIdx.x, cnt = 0;
    for (int base = 0; base < N; base += 32) {
        int l = labels[base + lane];
        bool mine = (l == c);
        unsigned mask = __ballot_sync(0xffffffffu, mine);
        if (mine) {
            int pos = cnt + __popc(mask & ((1u << lane) - 1u));
            g_class_members[c][pos] = base + lane;
            g_rank[base + lane] = pos;
        }
        cnt += __popc(mask);
    }
    if (lane == 0) g_class_count[c] = cnt;
}

// ---------------- z kernel (unchanged from R5) ----------------
__global__ __launch_bounds__(256, 2)
void z_kernel(const float* __restrict__ emb, const int* __restrict__ labels) {
    extern __shared__ char sm[];
    int*   rlab = reinterpret_cast<int*>(sm + OFF_RLAB);
    float* rci  = reinterpret_cast<float*>(sm + OFF_RCI);
    float* cjs  = reinterpret_cast<float*>(sm + OFF_CJ);
    int*   lc   = reinterpret_cast<int*>(sm + OFF_LC);
    const uint32_t smb = smem_u32(sm);

    const int tid  = threadIdx.x;
    const int wid  = tid >> 5;
    const int lane = tid & 31;
    const int warp_m = wid & 1;
    const int warp_n = wid >> 1;
    const int g = lane >> 2;
    const int t = lane & 3;

    const int r0   = blockIdx.x * BM;
    const int cbeg = blockIdx.y * COLS_PER_SPLIT;
    const float ASCALE = -2.f * L2E;

    for (int s = tid; s < BM * 16; s += 256) {
        int row = s >> 4, k0 = (s & 15) * 8;
        const float4* src = reinterpret_cast<const float4*>(emb + (size_t)(r0 + row) * DIM + k0);
        float4 v0 = src[0], v1 = src[1];
        float xs[8] = {v0.x * ASCALE, v0.y * ASCALE, v0.z * ASCALE, v0.w * ASCALE,
                       v1.x * ASCALE, v1.y * ASCALE, v1.z * ASCALE, v1.w * ASCALE};
        storeA8(sm + OFF_AHI, (uint32_t)(row * PITCHB + k0 * 2), xs);
    }
    if (tid < BM) {
        rlab[tid] = labels[r0 + tid];
        rci[tid]  = g_csq[r0 + tid];
    }

    const int mtx = lane >> 3, lrow = lane & 7;
    const uint32_t aoff = (uint32_t)((warp_m * 64 + (mtx & 1) * 8 + lrow) * PITCHB
                                     + ((mtx >> 1) * 8) * 2);
    const uint32_t boff = (uint32_t)((warp_n * 32 + (mtx >> 1) * 8 + lrow) * PITCHB
                                     + ((mtx & 1) * 8) * 2);
    const uint32_t aAhi = smb + OFF_AHI + aoff;
    const uint32_t aBhi = smb + OFF_BHI + boff;
    const uint32_t aBlo = smb + OFF_BLO + boff;

    int myl[8];
    float rowacc[8];
#pragma unroll
    for (int rr = 0; rr < 8; ++rr) rowacc[rr] = 0.f;

    for (int tile = 0; tile < TILES_PER_SPLIT; ++tile) {
        const int c0 = cbeg + tile * BN;
        __syncthreads();

        for (int s = tid; s < BN * 16; s += 256) {
            int row = s >> 4, k0 = (s & 15) * 8;
            const float4* src = reinterpret_cast<const float4*>(emb + (size_t)(c0 + row) * DIM + k0);
            float4 v0 = src[0], v1 = src[1];
            float xs[8] = {v0.x, v0.y, v0.z, v0.w, v1.x, v1.y, v1.z, v1.w};
            storeB8(sm + OFF_BHI, sm + OFF_BLO, (uint32_t)(row * PITCHB + k0 * 2), xs);
        }
        if (tid < BN) {
            cjs[tid] = g_csq[c0 + tid];
            lc[tid]  = labels[c0 + tid];
        }
        __syncthreads();

        float acc[16][4];
#pragma unroll
        for (int i = 0; i < 16; ++i)
#pragma unroll
            for (int j = 0; j < 4; ++j) acc[i][j] = 0.f;

#pragma unroll
        for (int ks = 0; ks < 8; ++ks) {
            const uint32_t kb = (uint32_t)ks * 32;
            uint32_t ah[4][4], bh[2][4], bl[2][4];
#pragma unroll
            for (int am = 0; am < 4; ++am)
                LDSM4(ah[am], aAhi + (uint32_t)am * (16 * PITCHB) + kb);
#pragma unroll
            for (int bn = 0; bn < 2; ++bn) {
                LDSM4(bh[bn], aBhi + (uint32_t)bn * (16 * PITCHB) + kb);
                LDSM4(bl[bn], aBlo + (uint32_t)bn * (16 * PITCHB) + kb);
            }
#pragma unroll
            for (int am = 0; am < 4; ++am)
#pragma unroll
                for (int na = 0; na < 4; ++na) {
                    const int bn = na >> 1, p = (na & 1) * 2;
                    mma16816(acc[am * 4 + na], ah[am], bh[bn][p], bh[bn][p + 1]);
                    mma16816(acc[am * 4 + na], ah[am], bl[bn][p], bl[bn][p + 1]);
                }
        }

        float cjv[8]; int ljv[8];
#pragma unroll
        for (int na = 0; na < 4; ++na)
#pragma unroll
            for (int cc = 0; cc < 2; ++cc) {
                int idx = na * 2 + cc;
                int nj = warp_n * 32 + na * 8 + 2 * t + cc;
                cjv[idx] = cjs[nj];
                ljv[idx] = lc[nj];
            }
#pragma unroll
        for (int am = 0; am < 4; ++am)
#pragma unroll
            for (int h = 0; h < 2; ++h) {
                const int rr = am * 2 + h;
                const int mloc = warp_m * 64 + am * 16 + h * 8 + g;
                if (tile == 0) myl[rr] = rlab[mloc];
                const int ml = myl[rr];
                float racc = rowacc[rr];
#pragma unroll
                for (int na = 0; na < 4; ++na)
#pragma unroll
                    for (int cc = 0; cc < 2; ++cc) {
                        const int idx = na * 2 + cc;
                        float tv = acc[am * 4 + na][h * 2 + cc] + cjv[idx];
                        if (ml != ljv[idx]) {
                            racc += ex2(tv);
                        } else {
                            int gi = r0 + mloc;
                            int gj = c0 + warp_n * 32 + na * 8 + 2 * t + cc;
                            if (gj > gi) {
                                float e = ex2(-(tv + rci[mloc]));
                                g_Dpair[ml][g_rank[gi]][g_rank[gj]] = e;
                            }
                        }
                    }
                rowacc[rr] = racc;
            }
    }

    __syncthreads();
    float* red = reinterpret_cast<float*>(sm + OFF_BHI);
#pragma unroll
    for (int am = 0; am < 4; ++am)
#pragma unroll
        for (int h = 0; h < 2; ++h) {
            int mloc = warp_m * 64 + am * 16 + h * 8 + g;
            red[mloc * 17 + warp_n * 4 + t] = rowacc[am * 2 + h];
        }
    __syncthreads();
    if (tid < BM) {
        float s = 0.f;
#pragma unroll
        for (int q = 0; q < 16; ++q) s += red[tid * 17 + q];
        g_Zpart[blockIdx.y][r0 + tid] = s * ex2(rci[tid]);
    }
}

// ---------------- pair kernel: one warp per anchor, table lookups ----------------
__global__ __launch_bounds__(256)
void pair3_kernel(const int* __restrict__ labels) {
    const int a    = (blockIdx.x * blockDim.x + threadIdx.x) >> 5;
    const int lane = threadIdx.x & 31;
    const int c = labels[a];
    const int p = g_rank[a];
    const int m = g_class_count[c];

    float Za = g_Zpart[0][a] + g_Zpart[1][a] + g_Zpart[2][a] + g_Zpart[3][a];

    float lsum = 0.f;
    for (int q = p + 1 + lane; q < m; q += 32)
        lsum += log1pf(Za * g_Dpair[c][p][q]);
#pragma unroll
    for (int off = 16; off > 0; off >>= 1)
        lsum += __shfl_xor_sync(0xffffffffu, lsum, off);
    if (lane == 0) g_rowsum[a] = lsum;
}

// ---------------- mean + final ----------------
__global__ void mean_kernel() {
    const int c = blockIdx.x, lane = threadIdx.x;
    const int m = g_class_count[c];
    float s = 0.f;
    for (int q = lane; q < m; q += 32) s += g_rowsum[g_class_members[c][q]];
#pragma unroll
    for (int off = 16; off > 0; off >>= 1) s += __shfl_xor_sync(0xffffffffu, s, off);
    if (lane == 0) {
        if (m >= 2) {
            float T = 0.5f * (float)m * (float)(m - 1);
            g_label_mean[c] = s / T;
            g_label_valid[c] = 1;
        } else { g_label_mean[c] = 0.f; g_label_valid[c] = 0; }
    }
}

__global__ void final_kernel(float* __restrict__ out) {
    if (threadIdx.x == 0) {
        float s = 0.f; int nv = 0;
        for (int c = 0; c < NCLS; ++c)
            if (g_label_valid[c]) { s += g_label_mean[c]; nv++; }
        out[0] = s / (float)(nv > 0 ? nv : 1);
    }
}

// ---------------- launch ----------------
extern "C" void kernel_launch(void* const* d_in, const int* in_sizes, int n_in,
                              void* d_out, int out_size) {
    const float* emb    = (const float*)d_in[0];
    const int*   labels = (const int*)d_in[1];
    float*       out    = (float*)d_out;

    static bool attr_set = false;
    if (!attr_set) {
        cudaFuncSetAttribute(z_kernel, cudaFuncAttributeMaxDynamicSharedMemorySize, Z_SMEM);
        attr_set = true;
    }

    sq_kernel<<<(N + 255) / 256, 256>>>(emb);
    classes_kernel<<<NCLS, 32>>>(labels);
    z_kernel<<<dim3(N / BM, KSPLIT), 256, Z_SMEM>>>(emb, labels);
    pair3_kernel<<<N / 8, 256>>>(labels);
    mean_kernel<<<NCLS, 32>>>();
    final_kernel<<<1, 32>>>(out);
}

// round 7
// speedup vs baseline: 10.1042x; 1.4708x over previous
#include <cuda_runtime.h>
#include <cuda_bf16.h>
#include <math.h>
#include <stdint.h>

#define N      8192
#define DIM    128
#define NCLS   64
#define BM     128
#define NT     (N / BM)          // 64 row tiles
#define NPAIRS (NT * (NT + 1) / 2)   // 2080
#define MAXMEM 8192
#define MAXM   256
#define L2E    1.4426950408889634f

#define PITCHB 272
#define TILE_BYTES (128 * PITCHB)

#define OFF_RLAB   0
#define OFF_RCI    512
#define OFF_CLAB   1024
#define OFF_CCJ    1536
#define OFF_COLRED 2048
#define OFF_AHI    2560
#define OFF_BHI    (OFF_AHI + TILE_BYTES)
#define OFF_BLO    (OFF_BHI + TILE_BYTES)
#define Z_SMEM     (OFF_BLO + TILE_BYTES)   // 107008 -> occ 2

// ---------------- helpers ----------------
__device__ __forceinline__ uint32_t smem_u32(const void* p) {
    uint32_t a;
    asm("{ .reg .u64 t; cvta.to.shared.u64 t, %1; cvt.u32.u64 %0, t; }" : "=r"(a) : "l"(p));
    return a;
}
__device__ __forceinline__ float ex2(float x) {
    float y;
    asm("ex2.approx.ftz.f32 %0, %1;" : "=f"(y) : "f"(x));
    return y;
}

#define LDSM4(r, addr) \
    asm volatile("ldmatrix.sync.aligned.m8n8.x4.shared.b16 {%0,%1,%2,%3}, [%4];" \
        : "=r"((r)[0]), "=r"((r)[1]), "=r"((r)[2]), "=r"((r)[3]) : "r"(addr))

__device__ __forceinline__ void mma16816(float* c, const uint32_t* a,
                                         uint32_t b0, uint32_t b1) {
    asm volatile(
        "mma.sync.aligned.m16n8k16.row.col.f32.bf16.bf16.f32 "
        "{%0,%1,%2,%3}, {%4,%5,%6,%7}, {%8,%9}, {%0,%1,%2,%3};"
        : "+f"(c[0]), "+f"(c[1]), "+f"(c[2]), "+f"(c[3])
        : "r"(a[0]), "r"(a[1]), "r"(a[2]), "r"(a[3]), "r"(b0), "r"(b1));
}

__device__ __forceinline__ void storeA8(char* base, uint32_t off, const float* xs) {
    uint32_t w[4];
#pragma unroll
    for (int p = 0; p < 4; ++p) {
        __nv_bfloat16 h0 = __float2bfloat16_rn(xs[2 * p]);
        __nv_bfloat16 h1 = __float2bfloat16_rn(xs[2 * p + 1]);
        w[p] = (uint32_t)__bfloat16_as_ushort(h0) | ((uint32_t)__bfloat16_as_ushort(h1) << 16);
    }
    *reinterpret_cast<uint4*>(base + off) = make_uint4(w[0], w[1], w[2], w[3]);
}
__device__ __forceinline__ void storeB8(char* bhi, char* blo, uint32_t off, const float* xs) {
    uint32_t hw[4], lw[4];
#pragma unroll
    for (int p = 0; p < 4; ++p) {
        float x0 = xs[2 * p], x1 = xs[2 * p + 1];
        __nv_bfloat16 h0 = __float2bfloat16_rn(x0);
        __nv_bfloat16 h1 = __float2bfloat16_rn(x1);
        __nv_bfloat16 l0 = __float2bfloat16_rn(x0 - __bfloat162float(h0));
        __nv_bfloat16 l1 = __float2bfloat16_rn(x1 - __bfloat162float(h1));
        hw[p] = (uint32_t)__bfloat16_as_ushort(h0) | ((uint32_t)__bfloat16_as_ushort(h1) << 16);
        lw[p] = (uint32_t)__bfloat16_as_ushort(l0) | ((uint32_t)__bfloat16_as_ushort(l1) << 16);
    }
    *reinterpret_cast<uint4*>(bhi + off) = make_uint4(hw[0], hw[1], hw[2], hw[3]);
    *reinterpret_cast<uint4*>(blo + off) = make_uint4(lw[0], lw[1], lw[2], lw[3]);
}

// ---------------- scratch ----------------
__device__ float g_sq[N];
__device__ float g_csq[N];
__device__ float g_Zmat[NT][N];     // slot s, row i: partial Z contribution (each cell written once)
__device__ float g_Z[N];
__device__ int   g_class_members[NCLS][MAXMEM];
__device__ int   g_class_count[NCLS];
__device__ int   g_rank[N];
__device__ float g_Dpair[NCLS][MAXM][MAXM];
__device__ float g_rowsum[N];
__device__ float g_label_mean[NCLS];
__device__ int   g_label_valid[NCLS];

// ---------------- kernel A: norms ----------------
__global__ void sq_kernel(const float* __restrict__ emb) {
    int i = blockIdx.x * blockDim.x + threadIdx.x;
    if (i >= N) return;
    const float4* row = reinterpret_cast<const float4*>(emb + (size_t)i * DIM);
    float s = 0.f;
#pragma unroll
    for (int t = 0; t < DIM / 4; ++t) {
        float4 v = row[t];
        s += v.x * v.x + v.y * v.y + v.z * v.z + v.w * v.w;
    }
    g_sq[i]  = s;
    g_csq[i] = s * L2E;
}

// ---------------- kernel B: member lists + ranks ----------------
__global__ void classes_kernel(const int* __restrict__ labels) {
    int c = blockIdx.x, lane = threadIdx.x, cnt = 0;
    for (int base = 0; base < N; base += 32) {
        int l = labels[base + lane];
        bool mine = (l == c);
        unsigned mask = __ballot_sync(0xffffffffu, mine);
        if (mine) {
            int pos = cnt + __popc(mask & ((1u << lane) - 1u));
            g_class_members[c][pos] = base + lane;
            g_rank[base + lane] = pos;
        }
        cnt += __popc(mask);
    }
    if (lane == 0) g_class_count[c] = cnt;
}

// ---------------- z kernel: one block per triangular tile pair ----------------
__global__ __launch_bounds__(256, 2)
void z_kernel(const float* __restrict__ emb, const int* __restrict__ labels) {
    extern __shared__ char sm[];
    int*   rlab   = reinterpret_cast<int*>(sm + OFF_RLAB);
    float* rci    = reinterpret_cast<float*>(sm + OFF_RCI);
    int*   clab   = reinterpret_cast<int*>(sm + OFF_CLAB);
    float* ccj    = reinterpret_cast<float*>(sm + OFF_CCJ);
    float* colred = reinterpret_cast<float*>(sm + OFF_COLRED);
    const uint32_t smb = smem_u32(sm);

    // triangular decode: block -> (bi, bj), bi <= bj
    int idx = blockIdx.x, bi = 0, rowlen = NT;
    while (idx >= rowlen) { idx -= rowlen; ++bi; --rowlen; }
    const int bj = bi + idx;
    const bool offdiag = (bi != bj);

    const int r0 = bi * BM;
    const int c0 = bj * BM;

    const int tid  = threadIdx.x;
    const int lane = tid & 31;
    const int wid  = tid >> 5;
    const int warp_m = wid & 1;
    const int warp_n = wid >> 1;
    const int g = lane >> 2;
    const int t = lane & 3;
    const float ASCALE = -2.f * L2E;

    // A tile: rows bi, scaled bf16 hi
    for (int s = tid; s < BM * 16; s += 256) {
        int row = s >> 4, k0 = (s & 15) * 8;
        const float4* src = reinterpret_cast<const float4*>(emb + (size_t)(r0 + row) * DIM + k0);
        float4 v0 = src[0], v1 = src[1];
        float xs[8] = {v0.x * ASCALE, v0.y * ASCALE, v0.z * ASCALE, v0.w * ASCALE,
                       v1.x * ASCALE, v1.y * ASCALE, v1.z * ASCALE, v1.w * ASCALE};
        storeA8(sm + OFF_AHI, (uint32_t)(row * PITCHB + k0 * 2), xs);
    }
    // B tile: rows bj, hi/lo split
    for (int s = tid; s < BM * 16; s += 256) {
        int row = s >> 4, k0 = (s & 15) * 8;
        const float4* src = reinterpret_cast<const float4*>(emb + (size_t)(c0 + row) * DIM + k0);
        float4 v0 = src[0], v1 = src[1];
        float xs[8] = {v0.x, v0.y, v0.z, v0.w, v1.x, v1.y, v1.z, v1.w};
        storeB8(sm + OFF_BHI, sm + OFF_BLO, (uint32_t)(row * PITCHB + k0 * 2), xs);
    }
    if (tid < BM) {
        rlab[tid] = labels[r0 + tid];
        rci[tid]  = g_csq[r0 + tid];
        clab[tid] = labels[c0 + tid];
        ccj[tid]  = g_csq[c0 + tid];
    }
    __syncthreads();

    // ldmatrix addresses
    const int mtx = lane >> 3, lrow = lane & 7;
    const uint32_t aoff = (uint32_t)((warp_m * 64 + (mtx & 1) * 8 + lrow) * PITCHB
                                     + ((mtx >> 1) * 8) * 2);
    const uint32_t boff = (uint32_t)((warp_n * 32 + (mtx >> 1) * 8 + lrow) * PITCHB
                                     + ((mtx & 1) * 8) * 2);
    const uint32_t aAhi = smb + OFF_AHI + aoff;
    const uint32_t aBhi = smb + OFF_BHI + boff;
    const uint32_t aBlo = smb + OFF_BLO + boff;

    // ---- mainloop ----
    float acc[16][4];
#pragma unroll
    for (int i = 0; i < 16; ++i)
#pragma unroll
        for (int j = 0; j < 4; ++j) acc[i][j] = 0.f;

#pragma unroll
    for (int ks = 0; ks < 8; ++ks) {
        const uint32_t kb = (uint32_t)ks * 32;
        uint32_t ah[4][4], bh[2][4], bl[2][4];
#pragma unroll
        for (int am = 0; am < 4; ++am)
            LDSM4(ah[am], aAhi + (uint32_t)am * (16 * PITCHB) + kb);
#pragma unroll
        for (int bn = 0; bn < 2; ++bn) {
            LDSM4(bh[bn], aBhi + (uint32_t)bn * (16 * PITCHB) + kb);
            LDSM4(bl[bn], aBlo + (uint32_t)bn * (16 * PITCHB) + kb);
        }
#pragma unroll
        for (int am = 0; am < 4; ++am)
#pragma unroll
            for (int na = 0; na < 4; ++na) {
                const int bn = na >> 1, p = (na & 1) * 2;
                mma16816(acc[am * 4 + na], ah[am], bh[bn][p], bh[bn][p + 1]);
                mma16816(acc[am * 4 + na], ah[am], bl[bn][p], bl[bn][p + 1]);
            }
    }

    // ---- epilogue: e = 2^(ci+cj-2*L2E*dot); row + col partials ----
    float rowacc[8], colacc[8];
#pragma unroll
    for (int i = 0; i < 8; ++i) { rowacc[i] = 0.f; colacc[i] = 0.f; }

    float cjv[8]; int ljv[8];
#pragma unroll
    for (int na = 0; na < 4; ++na)
#pragma unroll
        for (int cc = 0; cc < 2; ++cc) {
            int idx2 = na * 2 + cc;
            int nj = warp_n * 32 + na * 8 + 2 * t + cc;
            cjv[idx2] = ccj[nj];
            ljv[idx2] = clab[nj];
        }

#pragma unroll
    for (int am = 0; am < 4; ++am)
#pragma unroll
        for (int h = 0; h < 2; ++h) {
            const int rr = am * 2 + h;
            const int mloc = warp_m * 64 + am * 16 + h * 8 + g;
            const int ml = rlab[mloc];
            const float civ = rci[mloc];
            float racc = rowacc[rr];
#pragma unroll
            for (int na = 0; na < 4; ++na)
#pragma unroll
                for (int cc = 0; cc < 2; ++cc) {
                    const int idx2 = na * 2 + cc;
                    float tv = acc[am * 4 + na][h * 2 + cc] + cjv[idx2] + civ;
                    if (ml != ljv[idx2]) {
                        float e = ex2(tv);
                        racc += e;
                        colacc[idx2] += e;
                    } else {
                        int gi = r0 + mloc;
                        int gj = c0 + warp_n * 32 + na * 8 + 2 * t + cc;
                        if (gj > gi)
                            g_Dpair[ml][g_rank[gi]][g_rank[gj]] = ex2(-tv);
                    }
                }
            rowacc[rr] = racc;
        }

    // ---- column reduction (off-diagonal only) ----
    if (offdiag) {
#pragma unroll
        for (int i = 0; i < 8; ++i)
#pragma unroll
            for (int off = 4; off < 32; off <<= 1)
                colacc[i] += __shfl_xor_sync(0xffffffffu, colacc[i], off);
        if (warp_m == 0 && g == 0) {
#pragma unroll
            for (int na = 0; na < 4; ++na)
#pragma unroll
                for (int cc = 0; cc < 2; ++cc)
                    colred[warp_n * 32 + na * 8 + 2 * t + cc] = colacc[na * 2 + cc];
        }
    }
    __syncthreads();
    if (offdiag && warp_m == 1 && g == 0) {
#pragma unroll
        for (int na = 0; na < 4; ++na)
#pragma unroll
            for (int cc = 0; cc < 2; ++cc) {
                int col = warp_n * 32 + na * 8 + 2 * t + cc;
                g_Zmat[bi][c0 + col] = colred[col] + colacc[na * 2 + cc];
            }
    }

    // ---- row reduction (reuse Bhi region) ----
    float* red = reinterpret_cast<float*>(sm + OFF_BHI);   // [128][17]
#pragma unroll
    for (int am = 0; am < 4; ++am)
#pragma unroll
        for (int h = 0; h < 2; ++h) {
            int mloc = warp_m * 64 + am * 16 + h * 8 + g;
            red[mloc * 17 + warp_n * 4 + t] = rowacc[am * 2 + h];
        }
    __syncthreads();
    if (tid < BM) {
        float s = 0.f;
#pragma unroll
        for (int q = 0; q < 16; ++q) s += red[tid * 17 + q];
        g_Zmat[bj][r0 + tid] = s;
    }
}

// ---------------- Z assembly: sum 64 slots per row ----------------
__global__ void zsum_kernel() {
    int i = blockIdx.x * blockDim.x + threadIdx.x;
    float s = 0.f;
#pragma unroll
    for (int sl = 0; sl < NT; ++sl) s += g_Zmat[sl][i];
    g_Z[i] = s;
}

// ---------------- pair kernel: one warp per anchor, table lookups ----------------
__global__ __launch_bounds__(256)
void pair3_kernel(const int* __restrict__ labels) {
    const int a    = (blockIdx.x * blockDim.x + threadIdx.x) >> 5;
    const int lane = threadIdx.x & 31;
    const int c = labels[a];
    const int p = g_rank[a];
    const int m = g_class_count[c];

    float Za = g_Z[a];
    float lsum = 0.f;
    for (int q = p + 1 + lane; q < m; q += 32)
        lsum += log1pf(Za * g_Dpair[c][p][q]);
#pragma unroll
    for (int off = 16; off > 0; off >>= 1)
        lsum += __shfl_xor_sync(0xffffffffu, lsum, off);
    if (lane == 0) g_rowsum[a] = lsum;
}

// ---------------- mean + final ----------------
__global__ void mean_kernel() {
    const int c = blockIdx.x, lane = threadIdx.x;
    const int m = g_class_count[c];
    float s = 0.f;
    for (int q = lane; q < m; q += 32) s += g_rowsum[g_class_members[c][q]];
#pragma unroll
    for (int off = 16; off > 0; off >>= 1) s += __shfl_xor_sync(0xffffffffu, s, off);
    if (lane == 0) {
        if (m >= 2) {
            float T = 0.5f * (float)m * (float)(m - 1);
            g_label_mean[c] = s / T;
            g_label_valid[c] = 1;
        } else { g_label_mean[c] = 0.f; g_label_valid[c] = 0; }
    }
}

__global__ void final_kernel(float* __restrict__ out) {
    if (threadIdx.x == 0) {
        float s = 0.f; int nv = 0;
        for (int c = 0; c < NCLS; ++c)
            if (g_label_valid[c]) { s += g_label_mean[c]; nv++; }
        out[0] = s / (float)(nv > 0 ? nv : 1);
    }
}

// ---------------- launch ----------------
extern "C" void kernel_launch(void* const* d_in, const int* in_sizes, int n_in,
                              void* d_out, int out_size) {
    const float* emb    = (const float*)d_in[0];
    const int*   labels = (const int*)d_in[1];
    float*       out    = (float*)d_out;

    static bool attr_set = false;
    if (!attr_set) {
        cudaFuncSetAttribute(z_kernel, cudaFuncAttributeMaxDynamicSharedMemorySize, Z_SMEM);
        attr_set = true;
    }

    sq_kernel<<<(N + 255) / 256, 256>>>(emb);
    classes_kernel<<<NCLS, 32>>>(labels);
    z_kernel<<<NPAIRS, 256, Z_SMEM>>>(emb, labels);
    zsum_kernel<<<N / 256, 256>>>();
    pair3_kernel<<<N / 8, 256>>>(labels);
    mean_kernel<<<NCLS, 32>>>();
    final_kernel<<<1, 32>>>(out);
}

// round 8
// speedup vs baseline: 13.0386x; 1.2904x over previous
#include <cuda_runtime.h>
#include <cuda_fp16.h>
#include <math.h>
#include <stdint.h>

#define N      8192
#define DIM    128
#define NCLS   64
#define BM     128
#define NT     (N / BM)              // 64 row tiles
#define NPAIRS (NT * (NT + 1) / 2)   // 2080
#define MAXMEM 8192
#define MAXM   256
#define L2E    1.4426950408889634f

#define PITCHB 272
#define TILE_BYTES (128 * PITCHB)

#define OFF_RLAB   0
#define OFF_RCI    512
#define OFF_CLAB   1024
#define OFF_CCJ    1536
#define OFF_COLRED 2048
#define OFF_AH     2560
#define OFF_BH     (OFF_AH + TILE_BYTES)
#define Z_SMEM     (OFF_BH + TILE_BYTES)   // 72192

// ---------------- helpers ----------------
__device__ __forceinline__ uint32_t smem_u32(const void* p) {
    uint32_t a;
    asm("{ .reg .u64 t; cvta.to.shared.u64 t, %1; cvt.u32.u64 %0, t; }" : "=r"(a) : "l"(p));
    return a;
}
__device__ __forceinline__ float ex2(float x) {
    float y;
    asm("ex2.approx.ftz.f32 %0, %1;" : "=f"(y) : "f"(x));
    return y;
}

#define LDSM4(r, addr) \
    asm volatile("ldmatrix.sync.aligned.m8n8.x4.shared.b16 {%0,%1,%2,%3}, [%4];" \
        : "=r"((r)[0]), "=r"((r)[1]), "=r"((r)[2]), "=r"((r)[3]) : "r"(addr))

__device__ __forceinline__ void mma16816(float* c, const uint32_t* a,
                                         uint32_t b0, uint32_t b1) {
    asm volatile(
        "mma.sync.aligned.m16n8k16.row.col.f32.f16.f16.f32 "
        "{%0,%1,%2,%3}, {%4,%5,%6,%7}, {%8,%9}, {%0,%1,%2,%3};"
        : "+f"(c[0]), "+f"(c[1]), "+f"(c[2]), "+f"(c[3])
        : "r"(a[0]), "r"(a[1]), "r"(a[2]), "r"(a[3]), "r"(b0), "r"(b1));
}

// 8 floats -> 8 fp16 -> 16B store
__device__ __forceinline__ void storeH8(char* base, uint32_t off, const float* xs) {
    uint32_t w[4];
#pragma unroll
    for (int p = 0; p < 4; ++p) {
        __half2 h = __floats2half2_rn(xs[2 * p], xs[2 * p + 1]);
        w[p] = *reinterpret_cast<uint32_t*>(&h);
    }
    *reinterpret_cast<uint4*>(base + off) = make_uint4(w[0], w[1], w[2], w[3]);
}

// ---------------- scratch ----------------
__device__ float g_sq[N];
__device__ float g_csq[N];
__device__ float g_Zmat[NT][N];
__device__ int   g_class_members[NCLS][MAXMEM];
__device__ int   g_class_count[NCLS];
__device__ int   g_rank[N];
__device__ float g_Dpair[NCLS][MAXM][MAXM];
__device__ float g_rowsum[N];
__device__ float g_label_mean[NCLS];
__device__ int   g_label_valid[NCLS];

// ---------------- kernel A: norms ----------------
__global__ void sq_kernel(const float* __restrict__ emb) {
    int i = blockIdx.x * blockDim.x + threadIdx.x;
    if (i >= N) return;
    const float4* row = reinterpret_cast<const float4*>(emb + (size_t)i * DIM);
    float s = 0.f;
#pragma unroll
    for (int t = 0; t < DIM / 4; ++t) {
        float4 v = row[t];
        s += v.x * v.x + v.y * v.y + v.z * v.z + v.w * v.w;
    }
    g_sq[i]  = s;
    g_csq[i] = s * L2E;
}

// ---------------- kernel B: member lists + ranks ----------------
__global__ void classes_kernel(const int* __restrict__ labels) {
    int c = blockIdx.x, lane = threadIdx.x, cnt = 0;
    for (int base = 0; base < N; base += 32) {
        int l = labels[base + lane];
        bool mine = (l == c);
        unsigned mask = __ballot_sync(0xffffffffu, mine);
        if (mine) {
            int pos = cnt + __popc(mask & ((1u << lane) - 1u));
            g_class_members[c][pos] = base + lane;
            g_rank[base + lane] = pos;
        }
        cnt += __popc(mask);
    }
    if (lane == 0) g_class_count[c] = cnt;
}

// ---------------- z kernel: triangular tile pairs, single-pass fp16 ----------------
__global__ __launch_bounds__(256, 2)
void z_kernel(const float* __restrict__ emb, const int* __restrict__ labels) {
    extern __shared__ char sm[];
    int*   rlab   = reinterpret_cast<int*>(sm + OFF_RLAB);
    float* rci    = reinterpret_cast<float*>(sm + OFF_RCI);
    int*   clab   = reinterpret_cast<int*>(sm + OFF_CLAB);
    float* ccj    = reinterpret_cast<float*>(sm + OFF_CCJ);
    float* colred = reinterpret_cast<float*>(sm + OFF_COLRED);
    const uint32_t smb = smem_u32(sm);

    // triangular decode
    int idx = blockIdx.x, bi = 0, rowlen = NT;
    while (idx >= rowlen) { idx -= rowlen; ++bi; --rowlen; }
    const int bj = bi + idx;
    const bool offdiag = (bi != bj);

    const int r0 = bi * BM;
    const int c0 = bj * BM;

    const int tid  = threadIdx.x;
    const int lane = tid & 31;
    const int wid  = tid >> 5;
    const int warp_m = wid & 1;
    const int warp_n = wid >> 1;
    const int g = lane >> 2;
    const int t = lane & 3;
    const float ASCALE = -2.f * L2E;

    // A tile (scaled fp16) + B tile (fp16)
    for (int s = tid; s < BM * 16; s += 256) {
        int row = s >> 4, k0 = (s & 15) * 8;
        const float4* srcA = reinterpret_cast<const float4*>(emb + (size_t)(r0 + row) * DIM + k0);
        float4 a0 = srcA[0], a1 = srcA[1];
        float xa[8] = {a0.x * ASCALE, a0.y * ASCALE, a0.z * ASCALE, a0.w * ASCALE,
                       a1.x * ASCALE, a1.y * ASCALE, a1.z * ASCALE, a1.w * ASCALE};
        storeH8(sm + OFF_AH, (uint32_t)(row * PITCHB + k0 * 2), xa);

        const float4* srcB = reinterpret_cast<const float4*>(emb + (size_t)(c0 + row) * DIM + k0);
        float4 b0 = srcB[0], b1 = srcB[1];
        float xb[8] = {b0.x, b0.y, b0.z, b0.w, b1.x, b1.y, b1.z, b1.w};
        storeH8(sm + OFF_BH, (uint32_t)(row * PITCHB + k0 * 2), xb);
    }
    if (tid < BM) {
        rlab[tid] = labels[r0 + tid];
        rci[tid]  = g_csq[r0 + tid];
        clab[tid] = labels[c0 + tid];
        ccj[tid]  = g_csq[c0 + tid];
    }
    __syncthreads();

    const int mtx = lane >> 3, lrow = lane & 7;
    const uint32_t aoff = (uint32_t)((warp_m * 64 + (mtx & 1) * 8 + lrow) * PITCHB
                                     + ((mtx >> 1) * 8) * 2);
    const uint32_t boff = (uint32_t)((warp_n * 32 + (mtx >> 1) * 8 + lrow) * PITCHB
                                     + ((mtx & 1) * 8) * 2);
    const uint32_t aAh = smb + OFF_AH + aoff;
    const uint32_t aBh = smb + OFF_BH + boff;

    // ---- mainloop: single fp16 pass ----
    float acc[16][4];
#pragma unroll
    for (int i = 0; i < 16; ++i)
#pragma unroll
        for (int j = 0; j < 4; ++j) acc[i][j] = 0.f;

#pragma unroll
    for (int ks = 0; ks < 8; ++ks) {
        const uint32_t kb = (uint32_t)ks * 32;
        uint32_t ah[4][4], bh[2][4];
#pragma unroll
        for (int am = 0; am < 4; ++am)
            LDSM4(ah[am], aAh + (uint32_t)am * (16 * PITCHB) + kb);
#pragma unroll
        for (int bn = 0; bn < 2; ++bn)
            LDSM4(bh[bn], aBh + (uint32_t)bn * (16 * PITCHB) + kb);
#pragma unroll
        for (int am = 0; am < 4; ++am)
#pragma unroll
            for (int na = 0; na < 4; ++na) {
                const int bn = na >> 1, p = (na & 1) * 2;
                mma16816(acc[am * 4 + na], ah[am], bh[bn][p], bh[bn][p + 1]);
            }
    }

    // ---- epilogue: e = 2^(ci+cj-2*L2E*dot); row + col partials ----
    float rowacc[8], colacc[8];
#pragma unroll
    for (int i = 0; i < 8; ++i) { rowacc[i] = 0.f; colacc[i] = 0.f; }

    float cjv[8]; int ljv[8];
#pragma unroll
    for (int na = 0; na < 4; ++na)
#pragma unroll
        for (int cc = 0; cc < 2; ++cc) {
            int idx2 = na * 2 + cc;
            int nj = warp_n * 32 + na * 8 + 2 * t + cc;
            cjv[idx2] = ccj[nj];
            ljv[idx2] = clab[nj];
        }

#pragma unroll
    for (int am = 0; am < 4; ++am)
#pragma unroll
        for (int h = 0; h < 2; ++h) {
            const int rr = am * 2 + h;
            const int mloc = warp_m * 64 + am * 16 + h * 8 + g;
            const int ml = rlab[mloc];
            const float civ = rci[mloc];
            float racc = rowacc[rr];
#pragma unroll
            for (int na = 0; na < 4; ++na)
#pragma unroll
                for (int cc = 0; cc < 2; ++cc) {
                    const int idx2 = na * 2 + cc;
                    float tv = acc[am * 4 + na][h * 2 + cc] + cjv[idx2] + civ;
                    if (ml != ljv[idx2]) {
                        float e = ex2(tv);
                        racc += e;
                        colacc[idx2] += e;
                    } else {
                        int gi = r0 + mloc;
                        int gj = c0 + warp_n * 32 + na * 8 + 2 * t + cc;
                        if (gj > gi)
                            g_Dpair[ml][g_rank[gi]][g_rank[gj]] = ex2(-tv);
                    }
                }
            rowacc[rr] = racc;
        }

    // ---- column reduction (off-diagonal only) ----
    if (offdiag) {
#pragma unroll
        for (int i = 0; i < 8; ++i)
#pragma unroll
            for (int off = 4; off < 32; off <<= 1)
                colacc[i] += __shfl_xor_sync(0xffffffffu, colacc[i], off);
        if (warp_m == 0 && g == 0) {
#pragma unroll
            for (int na = 0; na < 4; ++na)
#pragma unroll
                for (int cc = 0; cc < 2; ++cc)
                    colred[warp_n * 32 + na * 8 + 2 * t + cc] = colacc[na * 2 + cc];
        }
    }
    __syncthreads();
    if (offdiag && warp_m == 1 && g == 0) {
#pragma unroll
        for (int na = 0; na < 4; ++na)
#pragma unroll
            for (int cc = 0; cc < 2; ++cc) {
                int col = warp_n * 32 + na * 8 + 2 * t + cc;
                g_Zmat[bi][c0 + col] = colred[col] + colacc[na * 2 + cc];
            }
    }

    // ---- row reduction (reuse B tile region) ----
    float* red = reinterpret_cast<float*>(sm + OFF_BH);   // [128][17]
#pragma unroll
    for (int am = 0; am < 4; ++am)
#pragma unroll
        for (int h = 0; h < 2; ++h) {
            int mloc = warp_m * 64 + am * 16 + h * 8 + g;
            red[mloc * 17 + warp_n * 4 + t] = rowacc[am * 2 + h];
        }
    __syncthreads();
    if (tid < BM) {
        float s = 0.f;
#pragma unroll
        for (int q = 0; q < 16; ++q) s += red[tid * 17 + q];
        g_Zmat[bj][r0 + tid] = s;
    }
}

// ---------------- pair kernel: warp per anchor, fused Z assembly ----------------
__global__ __launch_bounds__(256)
void pair3_kernel(const int* __restrict__ labels) {
    const int a    = (blockIdx.x * blockDim.x + threadIdx.x) >> 5;
    const int lane = threadIdx.x & 31;
    const int c = labels[a];
    const int p = g_rank[a];
    const int m = g_class_count[c];

    // Za = sum of 64 Zmat slots, lanes take 2 each, bfly-reduce (all lanes get Za)
    float Za = g_Zmat[lane][a] + g_Zmat[lane + 32][a];
#pragma unroll
    for (int off = 16; off > 0; off >>= 1)
        Za += __shfl_xor_sync(0xffffffffu, Za, off);

    float lsum = 0.f;
    for (int q = p + 1 + lane; q < m; q += 32)
        lsum += log1pf(Za * g_Dpair[c][p][q]);
#pragma unroll
    for (int off = 16; off > 0; off >>= 1)
        lsum += __shfl_xor_sync(0xffffffffu, lsum, off);
    if (lane == 0) g_rowsum[a] = lsum;
}

// ---------------- mean + final ----------------
__global__ void mean_kernel() {
    const int c = blockIdx.x, lane = threadIdx.x;
    const int m = g_class_count[c];
    float s = 0.f;
    for (int q = lane; q < m; q += 32) s += g_rowsum[g_class_members[c][q]];
#pragma unroll
    for (int off = 16; off > 0; off >>= 1) s += __shfl_xor_sync(0xffffffffu, s, off);
    if (lane == 0) {
        if (m >= 2) {
            float T = 0.5f * (float)m * (float)(m - 1);
            g_label_mean[c] = s / T;
            g_label_valid[c] = 1;
        } else { g_label_mean[c] = 0.f; g_label_valid[c] = 0; }
    }
}

__global__ void final_kernel(float* __restrict__ out) {
    if (threadIdx.x == 0) {
        float s = 0.f; int nv = 0;
        for (int c = 0; c < NCLS; ++c)
            if (g_label_valid[c]) { s += g_label_mean[c]; nv++; }
        out[0] = s / (float)(nv > 0 ? nv : 1);
    }
}

// ---------------- launch ----------------
extern "C" void kernel_launch(void* const* d_in, const int* in_sizes, int n_in,
                              void* d_out, int out_size) {
    const float* emb    = (const float*)d_in[0];
    const int*   labels = (const int*)d_in[1];
    float*       out    = (float*)d_out;

    static bool attr_set = false;
    if (!attr_set) {
        cudaFuncSetAttribute(z_kernel, cudaFuncAttributeMaxDynamicSharedMemorySize, Z_SMEM);
        attr_set = true;
    }

    sq_kernel<<<(N + 255) / 256, 256>>>(emb);
    classes_kernel<<<NCLS, 32>>>(labels);
    z_kernel<<<NPAIRS, 256, Z_SMEM>>>(emb, labels);
    pair3_kernel<<<N / 8, 256>>>(labels);
    mean_kernel<<<NCLS, 32>>>();
    final_kernel<<<1, 32>>>(out);
}

// round 9
// speedup vs baseline: 15.0874x; 1.1571x over previous
#include <cuda_runtime.h>
#include <cuda_fp16.h>
#include <math.h>
#include <stdint.h>

#define N      8192
#define DIM    128
#define NCLS   64
#define BM     128
#define NT     (N / BM)          // 64
#define NGRP   16                // column groups of 4 tiles
#define KT     4
#define NSLOT  (NT + NGRP)       // 80 Zmat slots
#define MAXMEM 8192
#define MAXM   256
#define L2E    1.4426950408889634f

#define PITCHB 272
#define TILE_BYTES (128 * PITCHB)

#define OFF_RLAB   0
#define OFF_RCI    512
#define OFF_CLAB   1024
#define OFF_CCJ    1536
#define OFF_COLRED 2048
#define OFF_AH     2560
#define OFF_BH     (OFF_AH + TILE_BYTES)
#define Z_SMEM     (OFF_BH + TILE_BYTES)   // ~72 KB -> occ 2

// ---------------- helpers ----------------
__device__ __forceinline__ uint32_t smem_u32(const void* p) {
    uint32_t a;
    asm("{ .reg .u64 t; cvta.to.shared.u64 t, %1; cvt.u32.u64 %0, t; }" : "=r"(a) : "l"(p));
    return a;
}
__device__ __forceinline__ float ex2(float x) {
    float y;
    asm("ex2.approx.ftz.f32 %0, %1;" : "=f"(y) : "f"(x));
    return y;
}
#define CP_ASYNC16(dst, src) \
    asm volatile("cp.async.cg.shared.global [%0], [%1], 16;" :: "r"(dst), "l"(src))
#define CP_COMMIT()  asm volatile("cp.async.commit_group;" ::: "memory")
#define CP_WAIT0()   asm volatile("cp.async.wait_group 0;" ::: "memory")

#define LDSM4(r, addr) \
    asm volatile("ldmatrix.sync.aligned.m8n8.x4.shared.b16 {%0,%1,%2,%3}, [%4];" \
        : "=r"((r)[0]), "=r"((r)[1]), "=r"((r)[2]), "=r"((r)[3]) : "r"(addr))

__device__ __forceinline__ void mma16816(float* c, const uint32_t* a,
                                         uint32_t b0, uint32_t b1) {
    asm volatile(
        "mma.sync.aligned.m16n8k16.row.col.f32.f16.f16.f32 "
        "{%0,%1,%2,%3}, {%4,%5,%6,%7}, {%8,%9}, {%0,%1,%2,%3};"
        : "+f"(c[0]), "+f"(c[1]), "+f"(c[2]), "+f"(c[3])
        : "r"(a[0]), "r"(a[1]), "r"(a[2]), "r"(a[3]), "r"(b0), "r"(b1));
}

// ---------------- scratch ----------------
__device__ __half g_embA[N * DIM];   // fp16, scaled by -2*L2E
__device__ __half g_embB[N * DIM];   // fp16, plain
__device__ float g_sq[N];
__device__ float g_csq[N];
__device__ float g_Zmat[NSLOT][N];
__device__ int   g_class_members[NCLS][MAXMEM];
__device__ int   g_class_count[NCLS];
__device__ int   g_rank[N];
__device__ float g_Dpair[NCLS][MAXM][MAXM];
__device__ float g_rowsum[N];
__device__ float g_label_mean[NCLS];
__device__ int   g_label_valid[NCLS];

// ---------------- prep: norms + fp16 conversion (warp per row) ----------------
__global__ void prep_kernel(const float* __restrict__ emb) {
    const int r    = (blockIdx.x * blockDim.x + threadIdx.x) >> 5;
    const int lane = threadIdx.x & 31;
    const float ASCALE = -2.f * L2E;

    float4 v = reinterpret_cast<const float4*>(emb + (size_t)r * DIM)[lane];
    float s = v.x * v.x + v.y * v.y + v.z * v.z + v.w * v.w;
#pragma unroll
    for (int off = 16; off > 0; off >>= 1)
        s += __shfl_xor_sync(0xffffffffu, s, off);
    if (lane == 0) { g_sq[r] = s; g_csq[r] = s * L2E; }

    __half2 b0 = __floats2half2_rn(v.x, v.y);
    __half2 b1 = __floats2half2_rn(v.z, v.w);
    __half2 a0 = __floats2half2_rn(v.x * ASCALE, v.y * ASCALE);
    __half2 a1 = __floats2half2_rn(v.z * ASCALE, v.w * ASCALE);
    reinterpret_cast<__half2*>(g_embB + (size_t)r * DIM)[lane * 2 + 0] = b0;
    reinterpret_cast<__half2*>(g_embB + (size_t)r * DIM)[lane * 2 + 1] = b1;
    reinterpret_cast<__half2*>(g_embA + (size_t)r * DIM)[lane * 2 + 0] = a0;
    reinterpret_cast<__half2*>(g_embA + (size_t)r * DIM)[lane * 2 + 1] = a1;
}

// ---------------- zero Zmat ----------------
__global__ void zinit_kernel() {
    int i = blockIdx.x * blockDim.x + threadIdx.x;
    reinterpret_cast<float4*>(g_Zmat)[i] = make_float4(0.f, 0.f, 0.f, 0.f);
}

// ---------------- member lists + ranks ----------------
__global__ void classes_kernel(const int* __restrict__ labels) {
    int c = blockIdx.x, lane = threadIdx.x, cnt = 0;
    for (int base = 0; base < N; base += 32) {
        int l = labels[base + lane];
        bool mine = (l == c);
        unsigned mask = __ballot_sync(0xffffffffu, mine);
        if (mine) {
            int pos = cnt + __popc(mask & ((1u << lane) - 1u));
            g_class_members[c][pos] = base + lane;
            g_rank[base + lane] = pos;
        }
        cnt += __popc(mask);
    }
    if (lane == 0) g_class_count[c] = cnt;
}

// ---------------- z kernel: strips of up to 4 tiles, cp.async fp16 tiles --------
__global__ __launch_bounds__(256, 2)
void z_kernel(const int* __restrict__ labels) {
    const int bi = blockIdx.x;
    const int gr = blockIdx.y;
    if (bi >= KT * gr + KT) return;     // strip entirely above diagonal row
    const int lo = (bi > KT * gr) ? bi : KT * gr;
    const int hi = KT * gr + KT;

    extern __shared__ char sm[];
    int*   rlab   = reinterpret_cast<int*>(sm + OFF_RLAB);
    float* rci    = reinterpret_cast<float*>(sm + OFF_RCI);
    int*   clab   = reinterpret_cast<int*>(sm + OFF_CLAB);
    float* ccj    = reinterpret_cast<float*>(sm + OFF_CCJ);
    float* colred = reinterpret_cast<float*>(sm + OFF_COLRED);
    const uint32_t smb = smem_u32(sm);

    const int tid  = threadIdx.x;
    const int lane = tid & 31;
    const int wid  = tid >> 5;
    const int warp_m = wid & 1;
    const int warp_n = wid >> 1;
    const int gq = lane >> 2;
    const int t  = lane & 3;

    const int r0 = bi * BM;

    // A tile via cp.async (16B chunks)
    for (int s = tid; s < 2048; s += 256) {
        int row = s >> 4, ch = s & 15;
        uint32_t dst = smb + OFF_AH + (uint32_t)(row * PITCHB + ch * 16);
        const __half* src = g_embA + (size_t)(r0 + row) * DIM + ch * 8;
        CP_ASYNC16(dst, src);
    }
    if (tid < BM) {
        rlab[tid] = labels[r0 + tid];
        rci[tid]  = g_csq[r0 + tid];
    }

    const int mtx = lane >> 3, lrow = lane & 7;
    const uint32_t aoff = (uint32_t)((warp_m * 64 + (mtx & 1) * 8 + lrow) * PITCHB
                                     + ((mtx >> 1) * 8) * 2);
    const uint32_t boff = (uint32_t)((warp_n * 32 + (mtx >> 1) * 8 + lrow) * PITCHB
                                     + ((mtx & 1) * 8) * 2);
    const uint32_t aAh = smb + OFF_AH + aoff;
    const uint32_t aBh = smb + OFF_BH + boff;

    float rowacc[8];
#pragma unroll
    for (int i = 0; i < 8; ++i) rowacc[i] = 0.f;

    for (int bj = lo; bj < hi; ++bj) {
        const int c0 = bj * BM;
        const bool offdiag = (bj != bi);

        for (int s = tid; s < 2048; s += 256) {
            int row = s >> 4, ch = s & 15;
            uint32_t dst = smb + OFF_BH + (uint32_t)(row * PITCHB + ch * 16);
            const __half* src = g_embB + (size_t)(c0 + row) * DIM + ch * 8;
            CP_ASYNC16(dst, src);
        }
        CP_COMMIT();
        if (tid < BM) {
            clab[tid] = labels[c0 + tid];
            ccj[tid]  = g_csq[c0 + tid];
        }
        CP_WAIT0();
        __syncthreads();

        // ---- MMA ----
        float acc[16][4];
#pragma unroll
        for (int i = 0; i < 16; ++i)
#pragma unroll
            for (int j = 0; j < 4; ++j) acc[i][j] = 0.f;

#pragma unroll
        for (int ks = 0; ks < 8; ++ks) {
            const uint32_t kb = (uint32_t)ks * 32;
            uint32_t ah[4][4], bh[2][4];
#pragma unroll
            for (int am = 0; am < 4; ++am)
                LDSM4(ah[am], aAh + (uint32_t)am * (16 * PITCHB) + kb);
#pragma unroll
            for (int bn = 0; bn < 2; ++bn)
                LDSM4(bh[bn], aBh + (uint32_t)bn * (16 * PITCHB) + kb);
#pragma unroll
            for (int am = 0; am < 4; ++am)
#pragma unroll
                for (int na = 0; na < 4; ++na) {
                    const int bn = na >> 1, p = (na & 1) * 2;
                    mma16816(acc[am * 4 + na], ah[am], bh[bn][p], bh[bn][p + 1]);
                }
        }

        // ---- epilogue ----
        float colacc[8];
#pragma unroll
        for (int i = 0; i < 8; ++i) colacc[i] = 0.f;

        float cjv[8]; int ljv[8];
#pragma unroll
        for (int na = 0; na < 4; ++na)
#pragma unroll
            for (int cc = 0; cc < 2; ++cc) {
                int idx2 = na * 2 + cc;
                int nj = warp_n * 32 + na * 8 + 2 * t + cc;
                cjv[idx2] = ccj[nj];
                ljv[idx2] = clab[nj];
            }

#pragma unroll
        for (int am = 0; am < 4; ++am)
#pragma unroll
            for (int h = 0; h < 2; ++h) {
                const int rr = am * 2 + h;
                const int mloc = warp_m * 64 + am * 16 + h * 8 + gq;
                const int ml = rlab[mloc];
                const float civ = rci[mloc];
                float pc[8];
#pragma unroll
                for (int i = 0; i < 8; ++i) pc[i] = cjv[i] + civ;
                float racc = rowacc[rr];
#pragma unroll
                for (int na = 0; na < 4; ++na)
#pragma unroll
                    for (int cc = 0; cc < 2; ++cc) {
                        const int idx2 = na * 2 + cc;
                        float tv = acc[am * 4 + na][h * 2 + cc] + pc[idx2];
                        if (ml != ljv[idx2]) {
                            float e = ex2(tv);
                            racc += e;
                            colacc[idx2] += e;
                        } else {
                            int gi = r0 + mloc;
                            int gj = c0 + warp_n * 32 + na * 8 + 2 * t + cc;
                            if (gj > gi)
                                g_Dpair[ml][g_rank[gi]][g_rank[gj]] = ex2(-tv);
                        }
                    }
                rowacc[rr] = racc;
            }

        // ---- column reduction (off-diagonal tiles only) ----
        if (offdiag) {
#pragma unroll
            for (int i = 0; i < 8; ++i)
#pragma unroll
                for (int off = 4; off < 32; off <<= 1)
                    colacc[i] += __shfl_xor_sync(0xffffffffu, colacc[i], off);
            if (warp_m == 0 && gq == 0) {
#pragma unroll
                for (int na = 0; na < 4; ++na)
#pragma unroll
                    for (int cc = 0; cc < 2; ++cc)
                        colred[warp_n * 32 + na * 8 + 2 * t + cc] = colacc[na * 2 + cc];
            }
        }
        __syncthreads();   // colred ready + B tile free for next iteration
        if (offdiag && warp_m == 1 && gq == 0) {
#pragma unroll
            for (int na = 0; na < 4; ++na)
#pragma unroll
                for (int cc = 0; cc < 2; ++cc) {
                    int col = warp_n * 32 + na * 8 + 2 * t + cc;
                    g_Zmat[bi][c0 + col] = colred[col] + colacc[na * 2 + cc];
                }
        }
    }

    // ---- row reduction once per block (reuse B tile region) ----
    __syncthreads();
    float* red = reinterpret_cast<float*>(sm + OFF_BH);   // [128][17]
#pragma unroll
    for (int am = 0; am < 4; ++am)
#pragma unroll
        for (int h = 0; h < 2; ++h) {
            int mloc = warp_m * 64 + am * 16 + h * 8 + gq;
            red[mloc * 17 + warp_n * 4 + t] = rowacc[am * 2 + h];
        }
    __syncthreads();
    if (tid < BM) {
        float s = 0.f;
#pragma unroll
        for (int q = 0; q < 16; ++q) s += red[tid * 17 + q];
        g_Zmat[NT + gr][r0 + tid] = s;
    }
}

// ---------------- pair kernel: warp per anchor, fused Z assembly (80 slots) ------
__global__ __launch_bounds__(256)
void pair3_kernel(const int* __restrict__ labels) {
    const int a    = (blockIdx.x * blockDim.x + threadIdx.x) >> 5;
    const int lane = threadIdx.x & 31;
    const int c = labels[a];
    const int p = g_rank[a];
    const int m = g_class_count[c];

    float Za = g_Zmat[lane][a] + g_Zmat[lane + 32][a];
    if (lane < NGRP) Za += g_Zmat[lane + 64][a];
#pragma unroll
    for (int off = 16; off > 0; off >>= 1)
        Za += __shfl_xor_sync(0xffffffffu, Za, off);

    float lsum = 0.f;
    for (int q = p + 1 + lane; q < m; q += 32)
        lsum += log1pf(Za * g_Dpair[c][p][q]);
#pragma unroll
    for (int off = 16; off > 0; off >>= 1)
        lsum += __shfl_xor_sync(0xffffffffu, lsum, off);
    if (lane == 0) g_rowsum[a] = lsum;
}

// ---------------- mean + final ----------------
__global__ void mean_kernel() {
    const int c = blockIdx.x, lane = threadIdx.x;
    const int m = g_class_count[c];
    float s = 0.f;
    for (int q = lane; q < m; q += 32) s += g_rowsum[g_class_members[c][q]];
#pragma unroll
    for (int off = 16; off > 0; off >>= 1) s += __shfl_xor_sync(0xffffffffu, s, off);
    if (lane == 0) {
        if (m >= 2) {
            float T = 0.5f * (float)m * (float)(m - 1);
            g_label_mean[c] = s / T;
            g_label_valid[c] = 1;
        } else { g_label_mean[c] = 0.f; g_label_valid[c] = 0; }
    }
}

__global__ void final_kernel(float* __restrict__ out) {
    if (threadIdx.x == 0) {
        float s = 0.f; int nv = 0;
        for (int c = 0; c < NCLS; ++c)
            if (g_label_valid[c]) { s += g_label_mean[c]; nv++; }
        out[0] = s / (float)(nv > 0 ? nv : 1);
    }
}

// ---------------- launch ----------------
extern "C" void kernel_launch(void* const* d_in, const int* in_sizes, int n_in,
                              void* d_out, int out_size) {
    const float* emb    = (const float*)d_in[0];
    const int*   labels = (const int*)d_in[1];
    float*       out    = (float*)d_out;

    static bool attr_set = false;
    if (!attr_set) {
        cudaFuncSetAttribute(z_kernel, cudaFuncAttributeMaxDynamicSharedMemorySize, Z_SMEM);
        attr_set = true;
    }

    prep_kernel<<<N / 8, 256>>>(emb);
    zinit_kernel<<<(NSLOT * N / 4) / 256, 256>>>();
    classes_kernel<<<NCLS, 32>>>(labels);
    z_kernel<<<dim3(NT, NGRP), 256, Z_SMEM>>>(labels);
    pair3_kernel<<<N / 8, 256>>>(labels);
    mean_kernel<<<NCLS, 32>>>();
    final_kernel<<<1, 32>>>(out);
}

// round 10
// speedup vs baseline: 15.4932x; 1.0269x over previous
#include <cuda_runtime.h>
#include <cuda_fp16.h>
#include <math.h>
#include <stdint.h>

#define N      8192
#define DIM    128
#define NCLS   64
#define BM     128
#define NT     (N / BM)          // 64
#define NGRP   8
#define KT     8
#define NSLOT  (NT + NGRP)       // 72
#define MAXM   256
#define L2E    1.4426950408889634f

#define PITCHB 272
#define TILE_BYTES (128 * PITCHB)

#define OFF_RCI    0
#define OFF_CCJ    512
#define OFF_COLRED 1024
#define OFF_AH     1536
#define OFF_BH     (OFF_AH + TILE_BYTES)
#define Z_SMEM     (OFF_BH + TILE_BYTES)   // 71168 -> occ 2

// ---------------- helpers ----------------
__device__ __forceinline__ uint32_t smem_u32(const void* p) {
    uint32_t a;
    asm("{ .reg .u64 t; cvta.to.shared.u64 t, %1; cvt.u32.u64 %0, t; }" : "=r"(a) : "l"(p));
    return a;
}
__device__ __forceinline__ float ex2(float x) {
    float y;
    asm("ex2.approx.ftz.f32 %0, %1;" : "=f"(y) : "f"(x));
    return y;
}
#define CP_ASYNC16(dst, src) \
    asm volatile("cp.async.cg.shared.global [%0], [%1], 16;" :: "r"(dst), "l"(src))
#define CP_COMMIT()  asm volatile("cp.async.commit_group;" ::: "memory")
#define CP_WAIT0()   asm volatile("cp.async.wait_group 0;" ::: "memory")

#define LDSM4(r, addr) \
    asm volatile("ldmatrix.sync.aligned.m8n8.x4.shared.b16 {%0,%1,%2,%3}, [%4];" \
        : "=r"((r)[0]), "=r"((r)[1]), "=r"((r)[2]), "=r"((r)[3]) : "r"(addr))

__device__ __forceinline__ void mma16816(float* c, const uint32_t* a,
                                         uint32_t b0, uint32_t b1) {
    asm volatile(
        "mma.sync.aligned.m16n8k16.row.col.f32.f16.f16.f32 "
        "{%0,%1,%2,%3}, {%4,%5,%6,%7}, {%8,%9}, {%0,%1,%2,%3};"
        : "+f"(c[0]), "+f"(c[1]), "+f"(c[2]), "+f"(c[3])
        : "r"(a[0]), "r"(a[1]), "r"(a[2]), "r"(a[3]), "r"(b0), "r"(b1));
}

// ---------------- scratch ----------------
__device__ __half g_embA[N * DIM];   // permuted by (class,rank), scaled by -2*L2E
__device__ __half g_embB[N * DIM];   // permuted, plain fp16
__device__ float g_csqP[N];          // permuted L2E*sq
__device__ int   g_cnt[NCLS];
__device__ int   g_off[NCLS + 1];
__device__ int   g_rank[N];
__device__ int   g_slotcls[N];
__device__ float g_Zmat[NSLOT][N];
__device__ float g_S[N];             // same-class row sums (correction)
__device__ float g_Dpair[NCLS][MAXM][MAXM];
__device__ float g_rowsum[N];
__device__ float g_label_mean[NCLS];
__device__ int   g_label_valid[NCLS];

// ---------------- classes: counts + ranks ----------------
__global__ void classes_kernel(const int* __restrict__ labels) {
    int c = blockIdx.x, lane = threadIdx.x, cnt = 0;
    for (int base = 0; base < N; base += 32) {
        int l = labels[base + lane];
        bool mine = (l == c);
        unsigned mask = __ballot_sync(0xffffffffu, mine);
        if (mine) g_rank[base + lane] = cnt + __popc(mask & ((1u << lane) - 1u));
        cnt += __popc(mask);
    }
    if (lane == 0) g_cnt[c] = cnt;
}

__global__ void offs_kernel() {
    if (threadIdx.x == 0) {
        int a = 0;
        for (int c = 0; c < NCLS; ++c) { g_off[c] = a; a += g_cnt[c]; }
        g_off[NCLS] = a;
    }
}

// ---------------- prep: permuted fp16 arrays + norms (warp per row) ----------------
__global__ void prep_kernel(const float* __restrict__ emb, const int* __restrict__ labels) {
    const int r    = (blockIdx.x * blockDim.x + threadIdx.x) >> 5;
    const int lane = threadIdx.x & 31;
    const float ASCALE = -2.f * L2E;

    float4 v = reinterpret_cast<const float4*>(emb + (size_t)r * DIM)[lane];
    float s = v.x * v.x + v.y * v.y + v.z * v.z + v.w * v.w;
#pragma unroll
    for (int off = 16; off > 0; off >>= 1)
        s += __shfl_xor_sync(0xffffffffu, s, off);

    const int lab  = labels[r];
    const int slot = g_off[lab] + g_rank[r];
    if (lane == 0) {
        g_csqP[slot]   = s * L2E;
        g_slotcls[slot] = lab;
    }
    reinterpret_cast<__half2*>(g_embB + (size_t)slot * DIM)[lane * 2 + 0] = __floats2half2_rn(v.x, v.y);
    reinterpret_cast<__half2*>(g_embB + (size_t)slot * DIM)[lane * 2 + 1] = __floats2half2_rn(v.z, v.w);
    reinterpret_cast<__half2*>(g_embA + (size_t)slot * DIM)[lane * 2 + 0] = __floats2half2_rn(v.x * ASCALE, v.y * ASCALE);
    reinterpret_cast<__half2*>(g_embA + (size_t)slot * DIM)[lane * 2 + 1] = __floats2half2_rn(v.z * ASCALE, v.w * ASCALE);
}

__global__ void zinit_kernel() {
    int i = blockIdx.x * blockDim.x + threadIdx.x;
    reinterpret_cast<float4*>(g_Zmat)[i] = make_float4(0.f, 0.f, 0.f, 0.f);
}

// ---------------- z kernel: pure GEMM + exp + row/col sums ----------------
__global__ __launch_bounds__(256, 2)
void z_kernel() {
    const int bi = blockIdx.x;
    const int gr = blockIdx.y;
    if (bi >= KT * gr + KT) return;
    const int lo = (bi > KT * gr) ? bi : KT * gr;
    const int hi = KT * gr + KT;

    extern __shared__ char sm[];
    float* rci    = reinterpret_cast<float*>(sm + OFF_RCI);
    float* ccj    = reinterpret_cast<float*>(sm + OFF_CCJ);
    float* colred = reinterpret_cast<float*>(sm + OFF_COLRED);
    const uint32_t smb = smem_u32(sm);

    const int tid  = threadIdx.x;
    const int lane = tid & 31;
    const int wid  = tid >> 5;
    const int warp_m = wid & 1;
    const int warp_n = wid >> 1;
    const int gq = lane >> 2;
    const int t  = lane & 3;

    const int r0 = bi * BM;

    for (int s = tid; s < 2048; s += 256) {
        int row = s >> 4, ch = s & 15;
        uint32_t dst = smb + OFF_AH + (uint32_t)(row * PITCHB + ch * 16);
        CP_ASYNC16(dst, g_embA + (size_t)(r0 + row) * DIM + ch * 8);
    }
    if (tid < BM) rci[tid] = g_csqP[r0 + tid];

    const int mtx = lane >> 3, lrow = lane & 7;
    const uint32_t aoff = (uint32_t)((warp_m * 64 + (mtx & 1) * 8 + lrow) * PITCHB
                                     + ((mtx >> 1) * 8) * 2);
    const uint32_t boff = (uint32_t)((warp_n * 32 + (mtx >> 1) * 8 + lrow) * PITCHB
                                     + ((mtx & 1) * 8) * 2);
    const uint32_t aAh = smb + OFF_AH + aoff;
    const uint32_t aBh = smb + OFF_BH + boff;

    float rowacc[8];
#pragma unroll
    for (int i = 0; i < 8; ++i) rowacc[i] = 0.f;

    for (int bj = lo; bj < hi; ++bj) {
        const int c0 = bj * BM;
        const bool offdiag = (bj != bi);

        for (int s = tid; s < 2048; s += 256) {
            int row = s >> 4, ch = s & 15;
            uint32_t dst = smb + OFF_BH + (uint32_t)(row * PITCHB + ch * 16);
            CP_ASYNC16(dst, g_embB + (size_t)(c0 + row) * DIM + ch * 8);
        }
        CP_COMMIT();
        if (tid < BM) ccj[tid] = g_csqP[c0 + tid];
        CP_WAIT0();
        __syncthreads();

        float acc[16][4];
#pragma unroll
        for (int i = 0; i < 16; ++i)
#pragma unroll
            for (int j = 0; j < 4; ++j) acc[i][j] = 0.f;

#pragma unroll
        for (int ks = 0; ks < 8; ++ks) {
            const uint32_t kb = (uint32_t)ks * 32;
            uint32_t ah[4][4], bh[2][4];
#pragma unroll
            for (int am = 0; am < 4; ++am)
                LDSM4(ah[am], aAh + (uint32_t)am * (16 * PITCHB) + kb);
#pragma unroll
            for (int bn = 0; bn < 2; ++bn)
                LDSM4(bh[bn], aBh + (uint32_t)bn * (16 * PITCHB) + kb);
#pragma unroll
            for (int am = 0; am < 4; ++am)
#pragma unroll
                for (int na = 0; na < 4; ++na) {
                    const int bn = na >> 1, p = (na & 1) * 2;
                    mma16816(acc[am * 4 + na], ah[am], bh[bn][p], bh[bn][p + 1]);
                }
        }

        // ---- clean epilogue: e = 2^(ci+cj-2*L2E*dot); row + col partials ----
        float colacc[8];
#pragma unroll
        for (int i = 0; i < 8; ++i) colacc[i] = 0.f;
        float cjv[8];
#pragma unroll
        for (int na = 0; na < 4; ++na)
#pragma unroll
            for (int cc = 0; cc < 2; ++cc)
                cjv[na * 2 + cc] = ccj[warp_n * 32 + na * 8 + 2 * t + cc];

#pragma unroll
        for (int am = 0; am < 4; ++am)
#pragma unroll
            for (int h = 0; h < 2; ++h) {
                const int rr = am * 2 + h;
                const float civ = rci[warp_m * 64 + am * 16 + h * 8 + gq];
                float pc[8];
#pragma unroll
                for (int i = 0; i < 8; ++i) pc[i] = cjv[i] + civ;
                float racc = rowacc[rr];
#pragma unroll
                for (int na = 0; na < 4; ++na)
#pragma unroll
                    for (int cc = 0; cc < 2; ++cc) {
                        const int idx2 = na * 2 + cc;
                        float e = ex2(acc[am * 4 + na][h * 2 + cc] + pc[idx2]);
                        racc += e;
                        colacc[idx2] += e;
                    }
                rowacc[rr] = racc;
            }

        if (offdiag) {
#pragma unroll
            for (int i = 0; i < 8; ++i)
#pragma unroll
                for (int off = 4; off < 32; off <<= 1)
                    colacc[i] += __shfl_xor_sync(0xffffffffu, colacc[i], off);
            if (warp_m == 0 && gq == 0) {
#pragma unroll
                for (int na = 0; na < 4; ++na)
#pragma unroll
                    for (int cc = 0; cc < 2; ++cc)
                        colred[warp_n * 32 + na * 8 + 2 * t + cc] = colacc[na * 2 + cc];
            }
        }
        __syncthreads();
        if (offdiag && warp_m == 1 && gq == 0) {
#pragma unroll
            for (int na = 0; na < 4; ++na)
#pragma unroll
                for (int cc = 0; cc < 2; ++cc) {
                    int col = warp_n * 32 + na * 8 + 2 * t + cc;
                    g_Zmat[bi][c0 + col] = colred[col] + colacc[na * 2 + cc];
                }
        }
    }

    __syncthreads();
    float* red = reinterpret_cast<float*>(sm + OFF_BH);   // [128][17]
#pragma unroll
    for (int am = 0; am < 4; ++am)
#pragma unroll
        for (int h = 0; h < 2; ++h) {
            int mloc = warp_m * 64 + am * 16 + h * 8 + gq;
            red[mloc * 17 + warp_n * 4 + t] = rowacc[am * 2 + h];
        }
    __syncthreads();
    if (tid < BM) {
        float s = 0.f;
#pragma unroll
        for (int q = 0; q < 16; ++q) s += red[tid * 17 + q];
        g_Zmat[NT + gr][r0 + tid] = s;
    }
}

// ---------------- per-class kernel: correction sums S + Dpair ----------------
__global__ __launch_bounds__(256, 2)
void cls_kernel() {
    const int c    = blockIdx.x;
    const int base = g_off[c];
    const int m    = g_off[c + 1] - base;
    if (m <= 0) return;
    const int ntc  = (m + 127) / 128;

    extern __shared__ char sm[];
    float* rci = reinterpret_cast<float*>(sm + OFF_RCI);
    float* ccj = reinterpret_cast<float*>(sm + OFF_CCJ);
    const uint32_t smb = smem_u32(sm);

    const int tid  = threadIdx.x;
    const int lane = tid & 31;
    const int wid  = tid >> 5;
    const int warp_m = wid & 1;
    const int warp_n = wid >> 1;
    const int gq = lane >> 2;
    const int t  = lane & 3;

    const int mtx = lane >> 3, lrow = lane & 7;
    const uint32_t aoff = (uint32_t)((warp_m * 64 + (mtx & 1) * 8 + lrow) * PITCHB
                                     + ((mtx >> 1) * 8) * 2);
    const uint32_t boff = (uint32_t)((warp_n * 32 + (mtx >> 1) * 8 + lrow) * PITCHB
                                     + ((mtx & 1) * 8) * 2);
    const uint32_t aAh = smb + OFF_AH + aoff;
    const uint32_t aBh = smb + OFF_BH + boff;

    for (int ti = 0; ti < ntc; ++ti) {
        const int ri = ti * 128;
        __syncthreads();   // prior A/red usage done
        for (int s = tid; s < 2048; s += 256) {
            int row = s >> 4, ch = s & 15;
            uint4 v = make_uint4(0, 0, 0, 0);
            if (ri + row < m)
                v = *reinterpret_cast<const uint4*>(g_embA + (size_t)(base + ri + row) * DIM + ch * 8);
            *reinterpret_cast<uint4*>(sm + OFF_AH + row * PITCHB + ch * 16) = v;
        }
        if (tid < BM) rci[tid] = (ri + tid < m) ? g_csqP[base + ri + tid] : 0.f;

        float rowacc[8];
#pragma unroll
        for (int i = 0; i < 8; ++i) rowacc[i] = 0.f;

        for (int tj = 0; tj < ntc; ++tj) {
            const int rj = tj * 128;
            __syncthreads();   // A visible / prior B consumed
            for (int s = tid; s < 2048; s += 256) {
                int row = s >> 4, ch = s & 15;
                uint4 v = make_uint4(0, 0, 0, 0);
                if (rj + row < m)
                    v = *reinterpret_cast<const uint4*>(g_embB + (size_t)(base + rj + row) * DIM + ch * 8);
                *reinterpret_cast<uint4*>(sm + OFF_BH + row * PITCHB + ch * 16) = v;
            }
            if (tid < BM) ccj[tid] = (rj + tid < m) ? g_csqP[base + rj + tid] : 0.f;
            __syncthreads();

            float acc[16][4];
#pragma unroll
            for (int i = 0; i < 16; ++i)
#pragma unroll
                for (int j = 0; j < 4; ++j) acc[i][j] = 0.f;

#pragma unroll
            for (int ks = 0; ks < 8; ++ks) {
                const uint32_t kb = (uint32_t)ks * 32;
                uint32_t ah[4][4], bh[2][4];
#pragma unroll
                for (int am = 0; am < 4; ++am)
                    LDSM4(ah[am], aAh + (uint32_t)am * (16 * PITCHB) + kb);
#pragma unroll
                for (int bn = 0; bn < 2; ++bn)
                    LDSM4(bh[bn], aBh + (uint32_t)bn * (16 * PITCHB) + kb);
#pragma unroll
                for (int am = 0; am < 4; ++am)
#pragma unroll
                    for (int na = 0; na < 4; ++na) {
                        const int bn = na >> 1, p = (na & 1) * 2;
                        mma16816(acc[am * 4 + na], ah[am], bh[bn][p], bh[bn][p + 1]);
                    }
            }

            // epilogue with bounds: accumulate S, store Dpair (q>p)
#pragma unroll
            for (int am = 0; am < 4; ++am)
#pragma unroll
                for (int h = 0; h < 2; ++h) {
                    const int rr = am * 2 + h;
                    const int mloc = warp_m * 64 + am * 16 + h * 8 + gq;
                    const int p = ri + mloc;
                    const float civ = rci[mloc];
#pragma unroll
                    for (int na = 0; na < 4; ++na)
#pragma unroll
                        for (int cc = 0; cc < 2; ++cc) {
                            int col = warp_n * 32 + na * 8 + 2 * t + cc;
                            int q = rj + col;
                            if (p < m && q < m) {
                                float tv = acc[am * 4 + na][h * 2 + cc] + ccj[col] + civ;
                                rowacc[rr] += ex2(tv);
                                if (q > p) g_Dpair[c][p][q] = ex2(-tv);
                            }
                        }
                }
        }

        __syncthreads();
        float* red = reinterpret_cast<float*>(sm + OFF_BH);
#pragma unroll
        for (int am = 0; am < 4; ++am)
#pragma unroll
            for (int h = 0; h < 2; ++h) {
                int mloc = warp_m * 64 + am * 16 + h * 8 + gq;
                red[mloc * 17 + warp_n * 4 + t] = rowacc[am * 2 + h];
            }
        __syncthreads();
        if (tid < BM && ri + tid < m) {
            float s = 0.f;
#pragma unroll
            for (int q = 0; q < 16; ++q) s += red[tid * 17 + q];
            g_S[base + ri + tid] = s;
        }
    }
}

// ---------------- pair kernel: warp per slot ----------------
__global__ __launch_bounds__(256)
void pair3_kernel() {
    const int s    = (blockIdx.x * blockDim.x + threadIdx.x) >> 5;
    const int lane = threadIdx.x & 31;
    const int c = g_slotcls[s];
    const int p = s - g_off[c];
    const int m = g_off[c + 1] - g_off[c];

    float Za = g_Zmat[lane][s] + g_Zmat[lane + 32][s];
    if (lane < NGRP) Za += g_Zmat[NT + lane][s];
#pragma unroll
    for (int off = 16; off > 0; off >>= 1)
        Za += __shfl_xor_sync(0xffffffffu, Za, off);
    Za -= g_S[s];   // remove same-class (incl. self) contamination

    float lsum = 0.f;
    for (int q = p + 1 + lane; q < m; q += 32)
        lsum += log1pf(Za * g_Dpair[c][p][q]);
#pragma unroll
    for (int off = 16; off > 0; off >>= 1)
        lsum += __shfl_xor_sync(0xffffffffu, lsum, off);
    if (lane == 0) g_rowsum[s] = lsum;
}

// ---------------- mean + final ----------------
__global__ void mean_kernel() {
    const int c = blockIdx.x, lane = threadIdx.x;
    const int base = g_off[c];
    const int m = g_off[c + 1] - base;
    float s = 0.f;
    for (int q = lane; q < m; q += 32) s += g_rowsum[base + q];
#pragma unroll
    for (int off = 16; off > 0; off >>= 1) s += __shfl_xor_sync(0xffffffffu, s, off);
    if (lane == 0) {
        if (m >= 2) {
            float T = 0.5f * (float)m * (float)(m - 1);
            g_label_mean[c] = s / T;
            g_label_valid[c] = 1;
        } else { g_label_mean[c] = 0.f; g_label_valid[c] = 0; }
    }
}

__global__ void final_kernel(float* __restrict__ out) {
    if (threadIdx.x == 0) {
        float s = 0.f; int nv = 0;
        for (int c = 0; c < NCLS; ++c)
            if (g_label_valid[c]) { s += g_label_mean[c]; nv++; }
        out[0] = s / (float)(nv > 0 ? nv : 1);
    }
}

// ---------------- launch ----------------
extern "C" void kernel_launch(void* const* d_in, const int* in_sizes, int n_in,
                              void* d_out, int out_size) {
    const float* emb    = (const float*)d_in[0];
    const int*   labels = (const int*)d_in[1];
    float*       out    = (float*)d_out;

    static bool attr_set = false;
    if (!attr_set) {
        cudaFuncSetAttribute(z_kernel,   cudaFuncAttributeMaxDynamicSharedMemorySize, Z_SMEM);
        cudaFuncSetAttribute(cls_kernel, cudaFuncAttributeMaxDynamicSharedMemorySize, Z_SMEM);
        attr_set = true;
    }

    classes_kernel<<<NCLS, 32>>>(labels);
    offs_kernel<<<1, 32>>>();
    prep_kernel<<<N / 8, 256>>>(emb, labels);
    zinit_kernel<<<(NSLOT * N / 4) / 256, 256>>>();
    z_kernel<<<dim3(NT, NGRP), 256, Z_SMEM>>>();
    cls_kernel<<<NCLS, 256, Z_SMEM>>>();
    pair3_kernel<<<N / 8, 256>>>();
    mean_kernel<<<NCLS, 32>>>();
    final_kernel<<<1, 32>>>(out);
}

// round 11
// speedup vs baseline: 17.0995x; 1.1037x over previous
#include <cuda_runtime.h>
#include <cuda_fp16.h>
#include <math.h>
#include <stdint.h>

#define N      8192
#define DIM    128
#define NCLS   64
#define BM     128
#define NT     (N / BM)          // 64
#define NGRP   8
#define KT     8
#define NSLOT  (NT + NGRP)       // 72
#define MAXM   256
#define L2E    1.4426950408889634f

#define PITCHB 272
#define TILE_BYTES (128 * PITCHB)

#define OFF_RCI    0
#define OFF_CCJ0   512
#define OFF_CCJ1   1024
#define OFF_COLRED 1536
#define OFF_AH     2048
#define OFF_BH0    (OFF_AH + TILE_BYTES)
#define OFF_BH1    (OFF_BH0 + TILE_BYTES)
#define Z_SMEM_Z   (OFF_BH1 + TILE_BYTES)   // 106496 -> occ 2
#define Z_SMEM_C   (OFF_BH1)                // cls: single B buffer

// ---------------- helpers ----------------
__device__ __forceinline__ uint32_t smem_u32(const void* p) {
    uint32_t a;
    asm("{ .reg .u64 t; cvta.to.shared.u64 t, %1; cvt.u32.u64 %0, t; }" : "=r"(a) : "l"(p));
    return a;
}
__device__ __forceinline__ float ex2(float x) {
    float y;
    asm("ex2.approx.ftz.f32 %0, %1;" : "=f"(y) : "f"(x));
    return y;
}
#define CP_ASYNC16(dst, src) \
    asm volatile("cp.async.cg.shared.global [%0], [%1], 16;" :: "r"(dst), "l"(src))
#define CP_COMMIT()  asm volatile("cp.async.commit_group;" ::: "memory")
#define CP_WAIT(n)   asm volatile("cp.async.wait_group %0;" :: "n"(n) : "memory")

#define LDSM4(r, addr) \
    asm volatile("ldmatrix.sync.aligned.m8n8.x4.shared.b16 {%0,%1,%2,%3}, [%4];" \
        : "=r"((r)[0]), "=r"((r)[1]), "=r"((r)[2]), "=r"((r)[3]) : "r"(addr))

__device__ __forceinline__ void mma16816(float* c, const uint32_t* a,
                                         uint32_t b0, uint32_t b1) {
    asm volatile(
        "mma.sync.aligned.m16n8k16.row.col.f32.f16.f16.f32 "
        "{%0,%1,%2,%3}, {%4,%5,%6,%7}, {%8,%9}, {%0,%1,%2,%3};"
        : "+f"(c[0]), "+f"(c[1]), "+f"(c[2]), "+f"(c[3])
        : "r"(a[0]), "r"(a[1]), "r"(a[2]), "r"(a[3]), "r"(b0), "r"(b1));
}

// ---------------- scratch ----------------
__device__ __half g_embA[N * DIM];   // permuted by (class,rank), scaled by -2*L2E
__device__ __half g_embB[N * DIM];   // permuted, plain fp16
__device__ float g_csqP[N];
__device__ int   g_cnt[NCLS];
__device__ int   g_off[NCLS + 1];
__device__ int   g_rank[N];
__device__ int   g_slotcls[N];
__device__ float g_Zmat[NSLOT][N];
__device__ float g_Spart[2][N];      // same-class row-sum partials (by tj)
__device__ float g_Dpair[NCLS][MAXM][MAXM];
__device__ float g_rowsum[N];
__device__ float g_label_mean[NCLS];
__device__ int   g_label_valid[NCLS];

// ---------------- classes: counts + ranks ----------------
__global__ void classes_kernel(const int* __restrict__ labels) {
    int c = blockIdx.x, lane = threadIdx.x, cnt = 0;
    for (int base = 0; base < N; base += 32) {
        int l = labels[base + lane];
        bool mine = (l == c);
        unsigned mask = __ballot_sync(0xffffffffu, mine);
        if (mine) g_rank[base + lane] = cnt + __popc(mask & ((1u << lane) - 1u));
        cnt += __popc(mask);
    }
    if (lane == 0) g_cnt[c] = cnt;
}

__global__ void offs_kernel() {
    if (threadIdx.x == 0) {
        int a = 0;
        for (int c = 0; c < NCLS; ++c) { g_off[c] = a; a += g_cnt[c]; }
        g_off[NCLS] = a;
    }
}

// ---------------- prep: permuted fp16 + norms + scratch zeroing ----------------
__global__ void prep_kernel(const float* __restrict__ emb, const int* __restrict__ labels) {
    const int gt   = blockIdx.x * blockDim.x + threadIdx.x;
    const int r    = gt >> 5;
    const int lane = threadIdx.x & 31;
    const float ASCALE = -2.f * L2E;

    // zero Zmat + Spart (grid covers it in one shot)
    if (gt < (NSLOT * N) / 4)
        reinterpret_cast<float4*>(g_Zmat)[gt] = make_float4(0.f, 0.f, 0.f, 0.f);
    if (gt < (2 * N) / 4)
        reinterpret_cast<float4*>(g_Spart)[gt] = make_float4(0.f, 0.f, 0.f, 0.f);

    float4 v = reinterpret_cast<const float4*>(emb + (size_t)r * DIM)[lane];
    float s = v.x * v.x + v.y * v.y + v.z * v.z + v.w * v.w;
#pragma unroll
    for (int off = 16; off > 0; off >>= 1)
        s += __shfl_xor_sync(0xffffffffu, s, off);

    const int lab  = labels[r];
    const int slot = g_off[lab] + g_rank[r];
    if (lane == 0) {
        g_csqP[slot]    = s * L2E;
        g_slotcls[slot] = lab;
    }
    reinterpret_cast<__half2*>(g_embB + (size_t)slot * DIM)[lane * 2 + 0] = __floats2half2_rn(v.x, v.y);
    reinterpret_cast<__half2*>(g_embB + (size_t)slot * DIM)[lane * 2 + 1] = __floats2half2_rn(v.z, v.w);
    reinterpret_cast<__half2*>(g_embA + (size_t)slot * DIM)[lane * 2 + 0] = __floats2half2_rn(v.x * ASCALE, v.y * ASCALE);
    reinterpret_cast<__half2*>(g_embA + (size_t)slot * DIM)[lane * 2 + 1] = __floats2half2_rn(v.z * ASCALE, v.w * ASCALE);
}

// ---------------- z kernel: double-buffered B, pure GEMM + exp ----------------
__global__ __launch_bounds__(256, 2)
void z_kernel() {
    const int bi = blockIdx.x;
    const int gr = blockIdx.y;
    if (bi >= KT * gr + KT) return;
    const int lo = (bi > KT * gr) ? bi : KT * gr;
    const int hi = KT * gr + KT;

    extern __shared__ char sm[];
    float* rci    = reinterpret_cast<float*>(sm + OFF_RCI);
    float* ccj0   = reinterpret_cast<float*>(sm + OFF_CCJ0);
    float* ccj1   = reinterpret_cast<float*>(sm + OFF_CCJ1);
    float* colred = reinterpret_cast<float*>(sm + OFF_COLRED);
    const uint32_t smb = smem_u32(sm);

    const int tid  = threadIdx.x;
    const int lane = tid & 31;
    const int wid  = tid >> 5;
    const int warp_m = wid & 1;
    const int warp_n = wid >> 1;
    const int gq = lane >> 2;
    const int t  = lane & 3;

    const int r0 = bi * BM;
    const uint32_t bufB[2] = {smb + OFF_BH0, smb + OFF_BH1};
    float* ccjb[2] = {ccj0, ccj1};

    // A tile (async)
    for (int s = tid; s < 2048; s += 256) {
        int row = s >> 4, ch = s & 15;
        CP_ASYNC16(smb + OFF_AH + (uint32_t)(row * PITCHB + ch * 16),
                   g_embA + (size_t)(r0 + row) * DIM + ch * 8);
    }
    if (tid < BM) rci[tid] = g_csqP[r0 + tid];

    // preload B[lo] into buf0 (group 0 = A + B0)
    for (int s = tid; s < 2048; s += 256) {
        int row = s >> 4, ch = s & 15;
        CP_ASYNC16(bufB[0] + (uint32_t)(row * PITCHB + ch * 16),
                   g_embB + (size_t)(lo * BM + row) * DIM + ch * 8);
    }
    if (tid < BM) ccj0[tid] = g_csqP[lo * BM + tid];
    CP_COMMIT();

    const int mtx = lane >> 3, lrow = lane & 7;
    const uint32_t aoff = (uint32_t)((warp_m * 64 + (mtx & 1) * 8 + lrow) * PITCHB
                                     + ((mtx >> 1) * 8) * 2);
    const uint32_t boff = (uint32_t)((warp_n * 32 + (mtx >> 1) * 8 + lrow) * PITCHB
                                     + ((mtx & 1) * 8) * 2);
    const uint32_t aAh = smb + OFF_AH + aoff;

    float rowacc[8];
#pragma unroll
    for (int i = 0; i < 8; ++i) rowacc[i] = 0.f;

    for (int bj = lo; bj < hi; ++bj) {
        const int cur = (bj - lo) & 1;
        const int c0 = bj * BM;
        const bool offdiag = (bj != bi);

        // preload next B tile into the other buffer
        if (bj + 1 < hi) {
            const int nc0 = (bj + 1) * BM;
            for (int s = tid; s < 2048; s += 256) {
                int row = s >> 4, ch = s & 15;
                CP_ASYNC16(bufB[cur ^ 1] + (uint32_t)(row * PITCHB + ch * 16),
                           g_embB + (size_t)(nc0 + row) * DIM + ch * 8);
            }
            if (tid < BM) ccjb[cur ^ 1][tid] = g_csqP[nc0 + tid];
            CP_COMMIT();
            CP_WAIT(1);
        } else {
            CP_WAIT(0);
        }
        __syncthreads();

        const uint32_t aBh = bufB[cur] + boff;
        const float* ccj = ccjb[cur];

        float acc[16][4];
#pragma unroll
        for (int i = 0; i < 16; ++i)
#pragma unroll
            for (int j = 0; j < 4; ++j) acc[i][j] = 0.f;

#pragma unroll
        for (int ks = 0; ks < 8; ++ks) {
            const uint32_t kb = (uint32_t)ks * 32;
            uint32_t ah[4][4], bh[2][4];
#pragma unroll
            for (int am = 0; am < 4; ++am)
                LDSM4(ah[am], aAh + (uint32_t)am * (16 * PITCHB) + kb);
#pragma unroll
            for (int bn = 0; bn < 2; ++bn)
                LDSM4(bh[bn], aBh + (uint32_t)bn * (16 * PITCHB) + kb);
#pragma unroll
            for (int am = 0; am < 4; ++am)
#pragma unroll
                for (int na = 0; na < 4; ++na) {
                    const int bn = na >> 1, p = (na & 1) * 2;
                    mma16816(acc[am * 4 + na], ah[am], bh[bn][p], bh[bn][p + 1]);
                }
        }

        // epilogue
        float colacc[8];
#pragma unroll
        for (int i = 0; i < 8; ++i) colacc[i] = 0.f;
        float cjv[8];
#pragma unroll
        for (int na = 0; na < 4; ++na)
#pragma unroll
            for (int cc = 0; cc < 2; ++cc)
                cjv[na * 2 + cc] = ccj[warp_n * 32 + na * 8 + 2 * t + cc];

#pragma unroll
        for (int am = 0; am < 4; ++am)
#pragma unroll
            for (int h = 0; h < 2; ++h) {
                const int rr = am * 2 + h;
                const float civ = rci[warp_m * 64 + am * 16 + h * 8 + gq];
                float pc[8];
#pragma unroll
                for (int i = 0; i < 8; ++i) pc[i] = cjv[i] + civ;
                float racc = rowacc[rr];
#pragma unroll
                for (int na = 0; na < 4; ++na)
#pragma unroll
                    for (int cc = 0; cc < 2; ++cc) {
                        const int idx2 = na * 2 + cc;
                        float e = ex2(acc[am * 4 + na][h * 2 + cc] + pc[idx2]);
                        racc += e;
                        colacc[idx2] += e;
                    }
                rowacc[rr] = racc;
            }

        if (offdiag) {
#pragma unroll
            for (int i = 0; i < 8; ++i)
#pragma unroll
                for (int off = 4; off < 32; off <<= 1)
                    colacc[i] += __shfl_xor_sync(0xffffffffu, colacc[i], off);
            if (warp_m == 0 && gq == 0) {
#pragma unroll
                for (int na = 0; na < 4; ++na)
#pragma unroll
                    for (int cc = 0; cc < 2; ++cc)
                        colred[warp_n * 32 + na * 8 + 2 * t + cc] = colacc[na * 2 + cc];
            }
        }
        __syncthreads();
        if (offdiag && warp_m == 1 && gq == 0) {
#pragma unroll
            for (int na = 0; na < 4; ++na)
#pragma unroll
                for (int cc = 0; cc < 2; ++cc) {
                    int col = warp_n * 32 + na * 8 + 2 * t + cc;
                    g_Zmat[bi][c0 + col] = colred[col] + colacc[na * 2 + cc];
                }
        }
    }

    __syncthreads();
    float* red = reinterpret_cast<float*>(sm + OFF_BH0);   // [128][17]
#pragma unroll
    for (int am = 0; am < 4; ++am)
#pragma unroll
        for (int h = 0; h < 2; ++h) {
            int mloc = warp_m * 64 + am * 16 + h * 8 + gq;
            red[mloc * 17 + warp_n * 4 + t] = rowacc[am * 2 + h];
        }
    __syncthreads();
    if (tid < BM) {
        float s = 0.f;
#pragma unroll
        for (int q = 0; q < 16; ++q) s += red[tid * 17 + q];
        g_Zmat[NT + gr][r0 + tid] = s;
    }
}

// ---------------- per-class correction: one block per (c, ti, tj) ----------------
__global__ __launch_bounds__(256, 2)
void cls_kernel() {
    const int c    = blockIdx.x;
    const int ti   = blockIdx.y;
    const int tj   = blockIdx.z;
    const int base = g_off[c];
    const int m    = g_off[c + 1] - base;
    const int ntc  = (m + 127) / 128;
    if (ti >= ntc || tj >= ntc) return;

    extern __shared__ char sm[];
    float* rci = reinterpret_cast<float*>(sm + OFF_RCI);
    float* ccj = reinterpret_cast<float*>(sm + OFF_CCJ0);
    const uint32_t smb = smem_u32(sm);

    const int tid  = threadIdx.x;
    const int lane = tid & 31;
    const int wid  = tid >> 5;
    const int warp_m = wid & 1;
    const int warp_n = wid >> 1;
    const int gq = lane >> 2;
    const int t  = lane & 3;

    const int ri = ti * 128, rj = tj * 128;

    for (int s = tid; s < 2048; s += 256) {
        int row = s >> 4, ch = s & 15;
        uint4 v = make_uint4(0, 0, 0, 0);
        if (ri + row < m)
            v = *reinterpret_cast<const uint4*>(g_embA + (size_t)(base + ri + row) * DIM + ch * 8);
        *reinterpret_cast<uint4*>(sm + OFF_AH + row * PITCHB + ch * 16) = v;

        uint4 w = make_uint4(0, 0, 0, 0);
        if (rj + row < m)
            w = *reinterpret_cast<const uint4*>(g_embB + (size_t)(base + rj + row) * DIM + ch * 8);
        *reinterpret_cast<uint4*>(sm + OFF_BH0 + row * PITCHB + ch * 16) = w;
    }
    if (tid < BM) {
        rci[tid] = (ri + tid < m) ? g_csqP[base + ri + tid] : 0.f;
        ccj[tid] = (rj + tid < m) ? g_csqP[base + rj + tid] : 0.f;
    }
    __syncthreads();

    const int mtx = lane >> 3, lrow = lane & 7;
    const uint32_t aoff = (uint32_t)((warp_m * 64 + (mtx & 1) * 8 + lrow) * PITCHB
                                     + ((mtx >> 1) * 8) * 2);
    const uint32_t boff = (uint32_t)((warp_n * 32 + (mtx >> 1) * 8 + lrow) * PITCHB
                                     + ((mtx & 1) * 8) * 2);
    const uint32_t aAh = smb + OFF_AH + aoff;
    const uint32_t aBh = smb + OFF_BH0 + boff;

    float acc[16][4];
#pragma unroll
    for (int i = 0; i < 16; ++i)
#pragma unroll
        for (int j = 0; j < 4; ++j) acc[i][j] = 0.f;

#pragma unroll
    for (int ks = 0; ks < 8; ++ks) {
        const uint32_t kb = (uint32_t)ks * 32;
        uint32_t ah[4][4], bh[2][4];
#pragma unroll
        for (int am = 0; am < 4; ++am)
            LDSM4(ah[am], aAh + (uint32_t)am * (16 * PITCHB) + kb);
#pragma unroll
        for (int bn = 0; bn < 2; ++bn)
            LDSM4(bh[bn], aBh + (uint32_t)bn * (16 * PITCHB) + kb);
#pragma unroll
        for (int am = 0; am < 4; ++am)
#pragma unroll
            for (int na = 0; na < 4; ++na) {
                const int bn = na >> 1, p = (na & 1) * 2;
                mma16816(acc[am * 4 + na], ah[am], bh[bn][p], bh[bn][p + 1]);
            }
    }

    float rowacc[8];
#pragma unroll
    for (int i = 0; i < 8; ++i) rowacc[i] = 0.f;

#pragma unroll
    for (int am = 0; am < 4; ++am)
#pragma unroll
        for (int h = 0; h < 2; ++h) {
            const int rr = am * 2 + h;
            const int mloc = warp_m * 64 + am * 16 + h * 8 + gq;
            const int p = ri + mloc;
            const float civ = rci[mloc];
#pragma unroll
            for (int na = 0; na < 4; ++na)
#pragma unroll
                for (int cc = 0; cc < 2; ++cc) {
                    int col = warp_n * 32 + na * 8 + 2 * t + cc;
                    int q = rj + col;
                    if (p < m && q < m) {
                        float tv = acc[am * 4 + na][h * 2 + cc] + ccj[col] + civ;
                        rowacc[rr] += ex2(tv);
                        if (q > p) g_Dpair[c][p][q] = ex2(-tv);
                    }
                }
        }

    __syncthreads();
    float* red = reinterpret_cast<float*>(sm + OFF_BH0);
#pragma unroll
    for (int am = 0; am < 4; ++am)
#pragma unroll
        for (int h = 0; h < 2; ++h) {
            int mloc = warp_m * 64 + am * 16 + h * 8 + gq;
            red[mloc * 17 + warp_n * 4 + t] = rowacc[am * 2 + h];
        }
    __syncthreads();
    if (tid < BM && ri + tid < m) {
        float s = 0.f;
#pragma unroll
        for (int q = 0; q < 16; ++q) s += red[tid * 17 + q];
        g_Spart[tj][base + ri + tid] = s;
    }
}

// ---------------- pair kernel: warp per slot ----------------
__global__ __launch_bounds__(256)
void pair3_kernel() {
    const int s    = (blockIdx.x * blockDim.x + threadIdx.x) >> 5;
    const int lane = threadIdx.x & 31;
    const int c = g_slotcls[s];
    const int p = s - g_off[c];
    const int m = g_off[c + 1] - g_off[c];

    float Za = g_Zmat[lane][s] + g_Zmat[lane + 32][s];
    if (lane < NGRP) Za += g_Zmat[NT + lane][s];
#pragma unroll
    for (int off = 16; off > 0; off >>= 1)
        Za += __shfl_xor_sync(0xffffffffu, Za, off);
    Za -= (g_Spart[0][s] + g_Spart[1][s]);   // remove same-class contamination

    float lsum = 0.f;
    for (int q = p + 1 + lane; q < m; q += 32)
        lsum += log1pf(Za * g_Dpair[c][p][q]);
#pragma unroll
    for (int off = 16; off > 0; off >>= 1)
        lsum += __shfl_xor_sync(0xffffffffu, lsum, off);
    if (lane == 0) g_rowsum[s] = lsum;
}

// ---------------- mean + final ----------------
__global__ void mean_kernel() {
    const int c = blockIdx.x, lane = threadIdx.x;
    const int base = g_off[c];
    const int m = g_off[c + 1] - base;
    float s = 0.f;
    for (int q = lane; q < m; q += 32) s += g_rowsum[base + q];
#pragma unroll
    for (int off = 16; off > 0; off >>= 1) s += __shfl_xor_sync(0xffffffffu, s, off);
    if (lane == 0) {
        if (m >= 2) {
            float T = 0.5f * (float)m * (float)(m - 1);
            g_label_mean[c] = s / T;
            g_label_valid[c] = 1;
        } else { g_label_mean[c] = 0.f; g_label_valid[c] = 0; }
    }
}

__global__ void final_kernel(float* __restrict__ out) {
    if (threadIdx.x == 0) {
        float s = 0.f; int nv = 0;
        for (int c = 0; c < NCLS; ++c)
            if (g_label_valid[c]) { s += g_label_mean[c]; nv++; }
        out[0] = s / (float)(nv > 0 ? nv : 1);
    }
}

// ---------------- launch ----------------
extern "C" void kernel_launch(void* const* d_in, const int* in_sizes, int n_in,
                              void* d_out, int out_size) {
    const float* emb    = (const float*)d_in[0];
    const int*   labels = (const int*)d_in[1];
    float*       out    = (float*)d_out;

    static bool attr_set = false;
    if (!attr_set) {
        cudaFuncSetAttribute(z_kernel,   cudaFuncAttributeMaxDynamicSharedMemorySize, Z_SMEM_Z);
        cudaFuncSetAttribute(cls_kernel, cudaFuncAttributeMaxDynamicSharedMemorySize, Z_SMEM_C);
        attr_set = true;
    }

    classes_kernel<<<NCLS, 32>>>(labels);
    offs_kernel<<<1, 32>>>();
    prep_kernel<<<N / 8, 256>>>(emb, labels);
    z_kernel<<<dim3(NT, NGRP), 256, Z_SMEM_Z>>>();
    cls_kernel<<<dim3(NCLS, 2, 2), 256, Z_SMEM_C>>>();
    pair3_kernel<<<N / 8, 256>>>();
    mean_kernel<<<NCLS, 32>>>();
    final_kernel<<<1, 32>>>(out);
}

// round 12
// speedup vs baseline: 20.6263x; 1.2063x over previous
#include <cuda_runtime.h>
#include <cuda_fp16.h>
#include <math.h>
#include <stdint.h>

#define N      8192
#define DIM    128
#define NCLS   64
#define BM     128
#define NT     (N / BM)          // 64
#define NGRP   8
#define KT     8
#define NSLOT  (NT + NGRP)       // 72
#define MAXM   256
#define L2E    1.4426950408889634f

#define PITCHB 272
#define TILE_BYTES (128 * PITCHB)

#define OFF_RCI    0
#define OFF_CCJ0   512
#define OFF_CCJ1   1024
#define OFF_COLRED 1536
#define OFF_AH     2048
#define OFF_BH0    (OFF_AH + TILE_BYTES)
#define OFF_BH1    (OFF_BH0 + TILE_BYTES)
#define Z_SMEM_Z   (OFF_BH1 + TILE_BYTES)   // 106496 -> occ 2

// ---------------- helpers ----------------
__device__ __forceinline__ uint32_t smem_u32(const void* p) {
    uint32_t a;
    asm("{ .reg .u64 t; cvta.to.shared.u64 t, %1; cvt.u32.u64 %0, t; }" : "=r"(a) : "l"(p));
    return a;
}
__device__ __forceinline__ float ex2(float x) {
    float y;
    asm("ex2.approx.ftz.f32 %0, %1;" : "=f"(y) : "f"(x));
    return y;
}
#define CP_ASYNC16(dst, src) \
    asm volatile("cp.async.cg.shared.global [%0], [%1], 16;" :: "r"(dst), "l"(src))
#define CP_COMMIT()  asm volatile("cp.async.commit_group;" ::: "memory")
#define CP_WAIT(n)   asm volatile("cp.async.wait_group %0;" :: "n"(n) : "memory")

#define LDSM4(r, addr) \
    asm volatile("ldmatrix.sync.aligned.m8n8.x4.shared.b16 {%0,%1,%2,%3}, [%4];" \
        : "=r"((r)[0]), "=r"((r)[1]), "=r"((r)[2]), "=r"((r)[3]) : "r"(addr))

__device__ __forceinline__ void mma16816(float* c, const uint32_t* a,
                                         uint32_t b0, uint32_t b1) {
    asm volatile(
        "mma.sync.aligned.m16n8k16.row.col.f32.f16.f16.f32 "
        "{%0,%1,%2,%3}, {%4,%5,%6,%7}, {%8,%9}, {%0,%1,%2,%3};"
        : "+f"(c[0]), "+f"(c[1]), "+f"(c[2]), "+f"(c[3])
        : "r"(a[0]), "r"(a[1]), "r"(a[2]), "r"(a[3]), "r"(b0), "r"(b1));
}

// ---------------- scratch ----------------
__device__ __half g_embA[N * DIM];
__device__ __half g_embB[N * DIM];
__device__ float g_csqP[N];
__device__ int   g_cnt[NCLS];
__device__ int   g_off[NCLS + 1];
__device__ int   g_rank[N];
__device__ int   g_slotcls[N];
__device__ float g_Zmat[NSLOT][N];
__device__ float g_S[N];
__device__ float g_Dpair[NCLS][MAXM][MAXM];
__device__ float g_rowsum[N];

// ---------------- classes: block per class, parallel segments ----------------
__global__ __launch_bounds__(256)
void classes_kernel(const int* __restrict__ labels) {
    const int c = blockIdx.x;
    const int tid = threadIdx.x, warp = tid >> 5, lane = tid & 31;
    __shared__ int segcnt[8];

    const int base0 = warp * 1024;
    int cnt = 0;
#pragma unroll 4
    for (int it = 0; it < 32; ++it) {
        int l = labels[base0 + it * 32 + lane];
        cnt += __popc(__ballot_sync(0xffffffffu, l == c));
    }
    if (lane == 0) segcnt[warp] = cnt;
    __syncthreads();
    int segoff = 0;
    for (int k = 0; k < warp; ++k) segoff += segcnt[k];
    cnt = segoff;
#pragma unroll 4
    for (int it = 0; it < 32; ++it) {
        int i = base0 + it * 32 + lane;
        bool mine = (labels[i] == c);
        unsigned mask = __ballot_sync(0xffffffffu, mine);
        if (mine) g_rank[i] = cnt + __popc(mask & ((1u << lane) - 1u));
        cnt += __popc(mask);
    }
    if (warp == 7 && lane == 0) g_cnt[c] = cnt;
}

// ---------------- prep: offsets + permuted fp16 + norms + zero Zmat ----------------
__global__ __launch_bounds__(256)
void prep_kernel(const float* __restrict__ emb, const int* __restrict__ labels) {
    __shared__ int s_off[NCLS + 1];
    const int tid  = threadIdx.x;
    const int gt   = blockIdx.x * blockDim.x + tid;
    const int r    = gt >> 5;
    const int lane = tid & 31;
    const float ASCALE = -2.f * L2E;

    if (tid < NCLS) s_off[tid + 1] = g_cnt[tid];
    // zero Zmat while waiting
    if (gt < (NSLOT * N) / 4)
        reinterpret_cast<float4*>(g_Zmat)[gt] = make_float4(0.f, 0.f, 0.f, 0.f);
    __syncthreads();
    if (tid == 0) {
        s_off[0] = 0;
        for (int c = 1; c <= NCLS; ++c) s_off[c] += s_off[c - 1];
    }
    __syncthreads();
    if (blockIdx.x == 0 && tid <= NCLS) g_off[tid] = s_off[tid];

    float4 v = reinterpret_cast<const float4*>(emb + (size_t)r * DIM)[lane];
    float s = v.x * v.x + v.y * v.y + v.z * v.z + v.w * v.w;
#pragma unroll
    for (int off = 16; off > 0; off >>= 1)
        s += __shfl_xor_sync(0xffffffffu, s, off);

    const int lab  = labels[r];
    const int slot = s_off[lab] + g_rank[r];
    if (lane == 0) {
        g_csqP[slot]    = s * L2E;
        g_slotcls[slot] = lab;
    }
    reinterpret_cast<__half2*>(g_embB + (size_t)slot * DIM)[lane * 2 + 0] = __floats2half2_rn(v.x, v.y);
    reinterpret_cast<__half2*>(g_embB + (size_t)slot * DIM)[lane * 2 + 1] = __floats2half2_rn(v.z, v.w);
    reinterpret_cast<__half2*>(g_embA + (size_t)slot * DIM)[lane * 2 + 0] = __floats2half2_rn(v.x * ASCALE, v.y * ASCALE);
    reinterpret_cast<__half2*>(g_embA + (size_t)slot * DIM)[lane * 2 + 1] = __floats2half2_rn(v.z * ASCALE, v.w * ASCALE);
}

// ---------------- zc kernel: z strips (gr<NGRP) + per-class correction (gr==NGRP) --
__global__ __launch_bounds__(256, 2)
void zc_kernel() {
    extern __shared__ char sm[];
    float* rci    = reinterpret_cast<float*>(sm + OFF_RCI);
    float* ccj0   = reinterpret_cast<float*>(sm + OFF_CCJ0);
    float* ccj1   = reinterpret_cast<float*>(sm + OFF_CCJ1);
    float* colred = reinterpret_cast<float*>(sm + OFF_COLRED);
    const uint32_t smb = smem_u32(sm);

    const int tid  = threadIdx.x;
    const int lane = tid & 31;
    const int wid  = tid >> 5;
    const int warp_m = wid & 1;
    const int warp_n = wid >> 1;
    const int gq = lane >> 2;
    const int t  = lane & 3;

    const int mtx = lane >> 3, lrow = lane & 7;
    const uint32_t aoff = (uint32_t)((warp_m * 64 + (mtx & 1) * 8 + lrow) * PITCHB
                                     + ((mtx >> 1) * 8) * 2);
    const uint32_t boff = (uint32_t)((warp_n * 32 + (mtx >> 1) * 8 + lrow) * PITCHB
                                     + ((mtx & 1) * 8) * 2);
    const uint32_t aAh = smb + OFF_AH + aoff;

    if (blockIdx.y == NGRP) {
        // ======== per-class correction path ========
        const int c    = blockIdx.x;
        const int base = g_off[c];
        const int m    = g_off[c + 1] - base;
        if (m <= 0) return;
        const int ntc  = (m + 127) / 128;
        const uint32_t aBh = smb + OFF_BH0 + boff;

        for (int ti = 0; ti < ntc; ++ti) {
            const int ri = ti * 128;
            __syncthreads();
            for (int s = tid; s < 2048; s += 256) {
                int row = s >> 4, ch = s & 15;
                uint4 v = make_uint4(0, 0, 0, 0);
                if (ri + row < m)
                    v = *reinterpret_cast<const uint4*>(g_embA + (size_t)(base + ri + row) * DIM + ch * 8);
                *reinterpret_cast<uint4*>(sm + OFF_AH + row * PITCHB + ch * 16) = v;
            }
            if (tid < BM) rci[tid] = (ri + tid < m) ? g_csqP[base + ri + tid] : 0.f;

            float rowacc[8];
#pragma unroll
            for (int i = 0; i < 8; ++i) rowacc[i] = 0.f;

            for (int tj = 0; tj < ntc; ++tj) {
                const int rj = tj * 128;
                __syncthreads();
                for (int s = tid; s < 2048; s += 256) {
                    int row = s >> 4, ch = s & 15;
                    uint4 w = make_uint4(0, 0, 0, 0);
                    if (rj + row < m)
                        w = *reinterpret_cast<const uint4*>(g_embB + (size_t)(base + rj + row) * DIM + ch * 8);
                    *reinterpret_cast<uint4*>(sm + OFF_BH0 + row * PITCHB + ch * 16) = w;
                }
                if (tid < BM) ccj0[tid] = (rj + tid < m) ? g_csqP[base + rj + tid] : 0.f;
                __syncthreads();

                float acc[16][4];
#pragma unroll
                for (int i = 0; i < 16; ++i)
#pragma unroll
                    for (int j = 0; j < 4; ++j) acc[i][j] = 0.f;
#pragma unroll
                for (int ks = 0; ks < 8; ++ks) {
                    const uint32_t kb = (uint32_t)ks * 32;
                    uint32_t ah[4][4], bh[2][4];
#pragma unroll
                    for (int am = 0; am < 4; ++am)
                        LDSM4(ah[am], aAh + (uint32_t)am * (16 * PITCHB) + kb);
#pragma unroll
                    for (int bn = 0; bn < 2; ++bn)
                        LDSM4(bh[bn], aBh + (uint32_t)bn * (16 * PITCHB) + kb);
#pragma unroll
                    for (int am = 0; am < 4; ++am)
#pragma unroll
                        for (int na = 0; na < 4; ++na) {
                            const int bn = na >> 1, p = (na & 1) * 2;
                            mma16816(acc[am * 4 + na], ah[am], bh[bn][p], bh[bn][p + 1]);
                        }
                }
#pragma unroll
                for (int am = 0; am < 4; ++am)
#pragma unroll
                    for (int h = 0; h < 2; ++h) {
                        const int rr = am * 2 + h;
                        const int mloc = warp_m * 64 + am * 16 + h * 8 + gq;
                        const int p = ri + mloc;
                        const float civ = rci[mloc];
#pragma unroll
                        for (int na = 0; na < 4; ++na)
#pragma unroll
                            for (int cc = 0; cc < 2; ++cc) {
                                int col = warp_n * 32 + na * 8 + 2 * t + cc;
                                int q = rj + col;
                                if (p < m && q < m) {
                                    float tv = acc[am * 4 + na][h * 2 + cc] + ccj0[col] + civ;
                                    rowacc[rr] += ex2(tv);
                                    if (q > p) g_Dpair[c][p][q] = ex2(-tv);
                                }
                            }
                    }
            }

            __syncthreads();
            float* red = reinterpret_cast<float*>(sm + OFF_BH0);
#pragma unroll
            for (int am = 0; am < 4; ++am)
#pragma unroll
                for (int h = 0; h < 2; ++h) {
                    int mloc = warp_m * 64 + am * 16 + h * 8 + gq;
                    red[mloc * 17 + warp_n * 4 + t] = rowacc[am * 2 + h];
                }
            __syncthreads();
            if (tid < BM && ri + tid < m) {
                float s = 0.f;
#pragma unroll
                for (int q = 0; q < 16; ++q) s += red[tid * 17 + q];
                g_S[base + ri + tid] = s;
            }
        }
        return;
    }

    // ======== z strip path ========
    const int bi = blockIdx.x;
    const int gr = blockIdx.y;
    if (bi >= KT * gr + KT) return;
    const int lo = (bi > KT * gr) ? bi : KT * gr;
    const int hi = KT * gr + KT;

    const int r0 = bi * BM;
    const uint32_t bufB[2] = {smb + OFF_BH0, smb + OFF_BH1};
    float* ccjb[2] = {ccj0, ccj1};

    for (int s = tid; s < 2048; s += 256) {
        int row = s >> 4, ch = s & 15;
        CP_ASYNC16(smb + OFF_AH + (uint32_t)(row * PITCHB + ch * 16),
                   g_embA + (size_t)(r0 + row) * DIM + ch * 8);
    }
    if (tid < BM) rci[tid] = g_csqP[r0 + tid];

    for (int s = tid; s < 2048; s += 256) {
        int row = s >> 4, ch = s & 15;
        CP_ASYNC16(bufB[0] + (uint32_t)(row * PITCHB + ch * 16),
                   g_embB + (size_t)(lo * BM + row) * DIM + ch * 8);
    }
    if (tid < BM) ccj0[tid] = g_csqP[lo * BM + tid];
    CP_COMMIT();

    float rowacc[8];
#pragma unroll
    for (int i = 0; i < 8; ++i) rowacc[i] = 0.f;

    for (int bj = lo; bj < hi; ++bj) {
        const int cur = (bj - lo) & 1;
        const int c0 = bj * BM;
        const bool offdiag = (bj != bi);

        if (bj + 1 < hi) {
            const int nc0 = (bj + 1) * BM;
            for (int s = tid; s < 2048; s += 256) {
                int row = s >> 4, ch = s & 15;
                CP_ASYNC16(bufB[cur ^ 1] + (uint32_t)(row * PITCHB + ch * 16),
                           g_embB + (size_t)(nc0 + row) * DIM + ch * 8);
            }
            if (tid < BM) ccjb[cur ^ 1][tid] = g_csqP[nc0 + tid];
            CP_COMMIT();
            CP_WAIT(1);
        } else {
            CP_WAIT(0);
        }
        __syncthreads();

        const uint32_t aBh = bufB[cur] + boff;
        const float* ccj = ccjb[cur];

        float acc[16][4];
#pragma unroll
        for (int i = 0; i < 16; ++i)
#pragma unroll
            for (int j = 0; j < 4; ++j) acc[i][j] = 0.f;

#pragma unroll
        for (int ks = 0; ks < 8; ++ks) {
            const uint32_t kb = (uint32_t)ks * 32;
            uint32_t ah[4][4], bh[2][4];
#pragma unroll
            for (int am = 0; am < 4; ++am)
                LDSM4(ah[am], aAh + (uint32_t)am * (16 * PITCHB) + kb);
#pragma unroll
            for (int bn = 0; bn < 2; ++bn)
                LDSM4(bh[bn], aBh + (uint32_t)bn * (16 * PITCHB) + kb);
#pragma unroll
            for (int am = 0; am < 4; ++am)
#pragma unroll
                for (int na = 0; na < 4; ++na) {
                    const int bn = na >> 1, p = (na & 1) * 2;
                    mma16816(acc[am * 4 + na], ah[am], bh[bn][p], bh[bn][p + 1]);
                }
        }

        float colacc[8];
#pragma unroll
        for (int i = 0; i < 8; ++i) colacc[i] = 0.f;
        float cjv[8];
#pragma unroll
        for (int na = 0; na < 4; ++na)
#pragma unroll
            for (int cc = 0; cc < 2; ++cc)
                cjv[na * 2 + cc] = ccj[warp_n * 32 + na * 8 + 2 * t + cc];

#pragma unroll
        for (int am = 0; am < 4; ++am)
#pragma unroll
            for (int h = 0; h < 2; ++h) {
                const int rr = am * 2 + h;
                const float civ = rci[warp_m * 64 + am * 16 + h * 8 + gq];
                float pc[8];
#pragma unroll
                for (int i = 0; i < 8; ++i) pc[i] = cjv[i] + civ;
                float racc = rowacc[rr];
#pragma unroll
                for (int na = 0; na < 4; ++na)
#pragma unroll
                    for (int cc = 0; cc < 2; ++cc) {
                        const int idx2 = na * 2 + cc;
                        float e = ex2(acc[am * 4 + na][h * 2 + cc] + pc[idx2]);
                        racc += e;
                        colacc[idx2] += e;
                    }
                rowacc[rr] = racc;
            }

        if (offdiag) {
#pragma unroll
            for (int i = 0; i < 8; ++i)
#pragma unroll
                for (int off = 4; off < 32; off <<= 1)
                    colacc[i] += __shfl_xor_sync(0xffffffffu, colacc[i], off);
            if (warp_m == 0 && gq == 0) {
#pragma unroll
                for (int na = 0; na < 4; ++na)
#pragma unroll
                    for (int cc = 0; cc < 2; ++cc)
                        colred[warp_n * 32 + na * 8 + 2 * t + cc] = colacc[na * 2 + cc];
            }
        }
        __syncthreads();
        if (offdiag && warp_m == 1 && gq == 0) {
#pragma unroll
            for (int na = 0; na < 4; ++na)
#pragma unroll
                for (int cc = 0; cc < 2; ++cc) {
                    int col = warp_n * 32 + na * 8 + 2 * t + cc;
                    g_Zmat[bi][c0 + col] = colred[col] + colacc[na * 2 + cc];
                }
        }
    }

    __syncthreads();
    float* red = reinterpret_cast<float*>(sm + OFF_BH0);
#pragma unroll
    for (int am = 0; am < 4; ++am)
#pragma unroll
        for (int h = 0; h < 2; ++h) {
            int mloc = warp_m * 64 + am * 16 + h * 8 + gq;
            red[mloc * 17 + warp_n * 4 + t] = rowacc[am * 2 + h];
        }
    __syncthreads();
    if (tid < BM) {
        float s = 0.f;
#pragma unroll
        for (int q = 0; q < 16; ++q) s += red[tid * 17 + q];
        g_Zmat[NT + gr][r0 + tid] = s;
    }
}

// ---------------- pair kernel: warp per slot ----------------
__global__ __launch_bounds__(256)
void pair3_kernel() {
    const int s    = (blockIdx.x * blockDim.x + threadIdx.x) >> 5;
    const int lane = threadIdx.x & 31;
    const int c = g_slotcls[s];
    const int p = s - g_off[c];
    const int m = g_off[c + 1] - g_off[c];

    float Za = g_Zmat[lane][s] + g_Zmat[lane + 32][s];
    if (lane < NGRP) Za += g_Zmat[NT + lane][s];
#pragma unroll
    for (int off = 16; off > 0; off >>= 1)
        Za += __shfl_xor_sync(0xffffffffu, Za, off);
    Za -= g_S[s];

    float lsum = 0.f;
    for (int q = p + 1 + lane; q < m; q += 32)
        lsum += log1pf(Za * g_Dpair[c][p][q]);
#pragma unroll
    for (int off = 16; off > 0; off >>= 1)
        lsum += __shfl_xor_sync(0xffffffffu, lsum, off);
    if (lane == 0) g_rowsum[s] = lsum;
}

// ---------------- finish: per-class means + final scalar, one block ----------------
__global__ __launch_bounds__(512)
void finish_kernel(float* __restrict__ out) {
    __shared__ float smean[NCLS];
    __shared__ int   svalid[NCLS];
    const int tid = threadIdx.x, warp = tid >> 5, lane = tid & 31;

    for (int c = warp * 4; c < warp * 4 + 4; ++c) {
        const int base = g_off[c];
        const int m = g_off[c + 1] - base;
        float s = 0.f;
        for (int q = lane; q < m; q += 32) s += g_rowsum[base + q];
#pragma unroll
        for (int off = 16; off > 0; off >>= 1)
            s += __shfl_xor_sync(0xffffffffu, s, off);
        if (lane == 0) {
            if (m >= 2) {
                smean[c]  = s / (0.5f * (float)m * (float)(m - 1));
                svalid[c] = 1;
            } else { smean[c] = 0.f; svalid[c] = 0; }
        }
    }
    __syncthreads();
    if (warp == 0) {
        float s  = smean[lane] + smean[lane + 32];
        int   nv = svalid[lane] + svalid[lane + 32];
#pragma unroll
        for (int off = 16; off > 0; off >>= 1) {
            s  += __shfl_xor_sync(0xffffffffu, s, off);
            nv += __shfl_xor_sync(0xffffffffu, nv, off);
        }
        if (lane == 0) out[0] = s / (float)(nv > 0 ? nv : 1);
    }
}

// ---------------- launch ----------------
extern "C" void kernel_launch(void* const* d_in, const int* in_sizes, int n_in,
                              void* d_out, int out_size) {
    const float* emb    = (const float*)d_in[0];
    const int*   labels = (const int*)d_in[1];
    float*       out    = (float*)d_out;

    static bool attr_set = false;
    if (!attr_set) {
        cudaFuncSetAttribute(zc_kernel, cudaFuncAttributeMaxDynamicSharedMemorySize, Z_SMEM_Z);
        attr_set = true;
    }

    classes_kernel<<<NCLS, 256>>>(labels);
    prep_kernel<<<N / 8, 256>>>(emb, labels);
    zc_kernel<<<dim3(NT, NGRP + 1), 256, Z_SMEM_Z>>>();
    pair3_kernel<<<N / 8, 256>>>();
    finish_kernel<<<1, 512>>>(out);
}

// round 13
// speedup vs baseline: 21.2588x; 1.0307x over previous
#include <cuda_runtime.h>
#include <cuda_fp16.h>
#include <math.h>
#include <stdint.h>

#define N      8192
#define DIM    128
#define NCLS   64
#define BM     128
#define NT     (N / BM)          // 64
#define NGRP   8
#define KT     8
#define NSLOT  (NT + NGRP)       // 72
#define MAXM   256
#define L2E    1.4426950408889634f
#define LN2    0.6931471805599453f

#define PITCHB 272
#define TILE_BYTES (128 * PITCHB)

#define OFF_RCI    0
#define OFF_CCJ0   512
#define OFF_CCJ1   1024
#define OFF_COLRED 1536
#define OFF_AH     2048
#define OFF_BH0    (OFF_AH + TILE_BYTES)
#define OFF_BH1    (OFF_BH0 + TILE_BYTES)
#define Z_SMEM_Z   (OFF_BH1 + TILE_BYTES)   // 106496 -> occ 2

// ---------------- helpers ----------------
__device__ __forceinline__ uint32_t smem_u32(const void* p) {
    uint32_t a;
    asm("{ .reg .u64 t; cvta.to.shared.u64 t, %1; cvt.u32.u64 %0, t; }" : "=r"(a) : "l"(p));
    return a;
}
__device__ __forceinline__ float ex2(float x) {
    float y;
    asm("ex2.approx.ftz.f32 %0, %1;" : "=f"(y) : "f"(x));
    return y;
}
__device__ __forceinline__ float lg2(float x) {
    float y;
    asm("lg2.approx.ftz.f32 %0, %1;" : "=f"(y) : "f"(x));
    return y;
}
// pack (lo, hi) fp32 -> f16x2 and take 2^x elementwise
__device__ __forceinline__ uint32_t pack_ex2_f16x2(float hi, float lo) {
    uint32_t h, e;
    asm("cvt.rn.f16x2.f32 %0, %1, %2;" : "=r"(h) : "f"(hi), "f"(lo));
    asm("ex2.approx.f16x2 %0, %1;" : "=r"(e) : "r"(h));
    return e;
}
__device__ __forceinline__ uint32_t hadd2u(uint32_t a, uint32_t b) {
    uint32_t d;
    asm("add.rn.f16x2 %0, %1, %2;" : "=r"(d) : "r"(a), "r"(b));
    return d;
}
__device__ __forceinline__ float2 f16x2_to_f2(uint32_t v) {
    __half2 h = *reinterpret_cast<__half2*>(&v);
    return __half22float2(h);
}

#define CP_ASYNC16(dst, src) \
    asm volatile("cp.async.cg.shared.global [%0], [%1], 16;" :: "r"(dst), "l"(src))
#define CP_COMMIT()  asm volatile("cp.async.commit_group;" ::: "memory")
#define CP_WAIT(n)   asm volatile("cp.async.wait_group %0;" :: "n"(n) : "memory")

#define LDSM4(r, addr) \
    asm volatile("ldmatrix.sync.aligned.m8n8.x4.shared.b16 {%0,%1,%2,%3}, [%4];" \
        : "=r"((r)[0]), "=r"((r)[1]), "=r"((r)[2]), "=r"((r)[3]) : "r"(addr))

__device__ __forceinline__ void mma16816(float* c, const uint32_t* a,
                                         uint32_t b0, uint32_t b1) {
    asm volatile(
        "mma.sync.aligned.m16n8k16.row.col.f32.f16.f16.f32 "
        "{%0,%1,%2,%3}, {%4,%5,%6,%7}, {%8,%9}, {%0,%1,%2,%3};"
        : "+f"(c[0]), "+f"(c[1]), "+f"(c[2]), "+f"(c[3])
        : "r"(a[0]), "r"(a[1]), "r"(a[2]), "r"(a[3]), "r"(b0), "r"(b1));
}

// ---------------- scratch ----------------
__device__ __half g_embA[N * DIM];
__device__ __half g_embB[N * DIM];
__device__ float g_csqP[N];
__device__ int   g_cnt[NCLS];
__device__ int   g_off[NCLS + 1];
__device__ int   g_rank[N];
__device__ int   g_slotcls[N];
__device__ float g_Zmat[NSLOT][N];
__device__ float g_S[N];
__device__ float g_Dpair[NCLS][MAXM][MAXM];
__device__ float g_rowsum[N];

// ---------------- classes: block per class, parallel segments ----------------
__global__ __launch_bounds__(256)
void classes_kernel(const int* __restrict__ labels) {
    const int c = blockIdx.x;
    const int tid = threadIdx.x, warp = tid >> 5, lane = tid & 31;
    __shared__ int segcnt[8];

    const int base0 = warp * 1024;
    int cnt = 0;
#pragma unroll 4
    for (int it = 0; it < 32; ++it) {
        int l = labels[base0 + it * 32 + lane];
        cnt += __popc(__ballot_sync(0xffffffffu, l == c));
    }
    if (lane == 0) segcnt[warp] = cnt;
    __syncthreads();
    int segoff = 0;
    for (int k = 0; k < warp; ++k) segoff += segcnt[k];
    cnt = segoff;
#pragma unroll 4
    for (int it = 0; it < 32; ++it) {
        int i = base0 + it * 32 + lane;
        bool mine = (labels[i] == c);
        unsigned mask = __ballot_sync(0xffffffffu, mine);
        if (mine) g_rank[i] = cnt + __popc(mask & ((1u << lane) - 1u));
        cnt += __popc(mask);
    }
    if (warp == 7 && lane == 0) g_cnt[c] = cnt;
}

// ---------------- prep: offsets + permuted fp16 + norms + zero Zmat ----------------
__global__ __launch_bounds__(256)
void prep_kernel(const float* __restrict__ emb, const int* __restrict__ labels) {
    __shared__ int s_off[NCLS + 1];
    const int tid  = threadIdx.x;
    const int gt   = blockIdx.x * blockDim.x + tid;
    const int r    = gt >> 5;
    const int lane = tid & 31;
    const float ASCALE = -2.f * L2E;

    if (tid < NCLS) s_off[tid + 1] = g_cnt[tid];
    if (gt < (NSLOT * N) / 4)
        reinterpret_cast<float4*>(g_Zmat)[gt] = make_float4(0.f, 0.f, 0.f, 0.f);
    __syncthreads();
    if (tid == 0) {
        s_off[0] = 0;
        for (int c = 1; c <= NCLS; ++c) s_off[c] += s_off[c - 1];
    }
    __syncthreads();
    if (blockIdx.x == 0 && tid <= NCLS) g_off[tid] = s_off[tid];

    float4 v = reinterpret_cast<const float4*>(emb + (size_t)r * DIM)[lane];
    float s = v.x * v.x + v.y * v.y + v.z * v.z + v.w * v.w;
#pragma unroll
    for (int off = 16; off > 0; off >>= 1)
        s += __shfl_xor_sync(0xffffffffu, s, off);

    const int lab  = labels[r];
    const int slot = s_off[lab] + g_rank[r];
    if (lane == 0) {
        g_csqP[slot]    = s * L2E;
        g_slotcls[slot] = lab;
    }
    reinterpret_cast<__half2*>(g_embB + (size_t)slot * DIM)[lane * 2 + 0] = __floats2half2_rn(v.x, v.y);
    reinterpret_cast<__half2*>(g_embB + (size_t)slot * DIM)[lane * 2 + 1] = __floats2half2_rn(v.z, v.w);
    reinterpret_cast<__half2*>(g_embA + (size_t)slot * DIM)[lane * 2 + 0] = __floats2half2_rn(v.x * ASCALE, v.y * ASCALE);
    reinterpret_cast<__half2*>(g_embA + (size_t)slot * DIM)[lane * 2 + 1] = __floats2half2_rn(v.z * ASCALE, v.w * ASCALE);
}

// ---------------- zc kernel: z strips (gr<NGRP) + per-class correction (gr==NGRP) --
__global__ __launch_bounds__(256, 2)
void zc_kernel() {
    extern __shared__ char sm[];
    float*    rci     = reinterpret_cast<float*>(sm + OFF_RCI);
    float*    ccj0    = reinterpret_cast<float*>(sm + OFF_CCJ0);
    float*    ccj1    = reinterpret_cast<float*>(sm + OFF_CCJ1);
    uint32_t* colred2 = reinterpret_cast<uint32_t*>(sm + OFF_COLRED);
    const uint32_t smb = smem_u32(sm);

    const int tid  = threadIdx.x;
    const int lane = tid & 31;
    const int wid  = tid >> 5;
    const int warp_m = wid & 1;
    const int warp_n = wid >> 1;
    const int gq = lane >> 2;
    const int t  = lane & 3;

    const int mtx = lane >> 3, lrow = lane & 7;
    const uint32_t aoff = (uint32_t)((warp_m * 64 + (mtx & 1) * 8 + lrow) * PITCHB
                                     + ((mtx >> 1) * 8) * 2);
    const uint32_t boff = (uint32_t)((warp_n * 32 + (mtx >> 1) * 8 + lrow) * PITCHB
                                     + ((mtx & 1) * 8) * 2);
    const uint32_t aAh = smb + OFF_AH + aoff;

    if (blockIdx.y == NGRP) {
        // ======== per-class correction path (fp32, exact-path for Dpair/S) ========
        const int c    = blockIdx.x;
        const int base = g_off[c];
        const int m    = g_off[c + 1] - base;
        if (m <= 0) return;
        const int ntc  = (m + 127) / 128;
        const uint32_t aBh = smb + OFF_BH0 + boff;

        for (int ti = 0; ti < ntc; ++ti) {
            const int ri = ti * 128;
            __syncthreads();
            for (int s = tid; s < 2048; s += 256) {
                int row = s >> 4, ch = s & 15;
                uint4 v = make_uint4(0, 0, 0, 0);
                if (ri + row < m)
                    v = *reinterpret_cast<const uint4*>(g_embA + (size_t)(base + ri + row) * DIM + ch * 8);
                *reinterpret_cast<uint4*>(sm + OFF_AH + row * PITCHB + ch * 16) = v;
            }
            if (tid < BM) rci[tid] = (ri + tid < m) ? g_csqP[base + ri + tid] : 0.f;

            float rowacc[8];
#pragma unroll
            for (int i = 0; i < 8; ++i) rowacc[i] = 0.f;

            for (int tj = 0; tj < ntc; ++tj) {
                const int rj = tj * 128;
                __syncthreads();
                for (int s = tid; s < 2048; s += 256) {
                    int row = s >> 4, ch = s & 15;
                    uint4 w = make_uint4(0, 0, 0, 0);
                    if (rj + row < m)
                        w = *reinterpret_cast<const uint4*>(g_embB + (size_t)(base + rj + row) * DIM + ch * 8);
                    *reinterpret_cast<uint4*>(sm + OFF_BH0 + row * PITCHB + ch * 16) = w;
                }
                if (tid < BM) ccj0[tid] = (rj + tid < m) ? g_csqP[base + rj + tid] : 0.f;
                __syncthreads();

                float acc[16][4];
#pragma unroll
                for (int i = 0; i < 16; ++i)
#pragma unroll
                    for (int j = 0; j < 4; ++j) acc[i][j] = 0.f;
#pragma unroll
                for (int ks = 0; ks < 8; ++ks) {
                    const uint32_t kb = (uint32_t)ks * 32;
                    uint32_t ah[4][4], bh[2][4];
#pragma unroll
                    for (int am = 0; am < 4; ++am)
                        LDSM4(ah[am], aAh + (uint32_t)am * (16 * PITCHB) + kb);
#pragma unroll
                    for (int bn = 0; bn < 2; ++bn)
                        LDSM4(bh[bn], aBh + (uint32_t)bn * (16 * PITCHB) + kb);
#pragma unroll
                    for (int am = 0; am < 4; ++am)
#pragma unroll
                        for (int na = 0; na < 4; ++na) {
                            const int bn = na >> 1, p = (na & 1) * 2;
                            mma16816(acc[am * 4 + na], ah[am], bh[bn][p], bh[bn][p + 1]);
                        }
                }
#pragma unroll
                for (int am = 0; am < 4; ++am)
#pragma unroll
                    for (int h = 0; h < 2; ++h) {
                        const int rr = am * 2 + h;
                        const int mloc = warp_m * 64 + am * 16 + h * 8 + gq;
                        const int p = ri + mloc;
                        const float civ = rci[mloc];
#pragma unroll
                        for (int na = 0; na < 4; ++na)
#pragma unroll
                            for (int cc = 0; cc < 2; ++cc) {
                                int col = warp_n * 32 + na * 8 + 2 * t + cc;
                                int q = rj + col;
                                if (p < m && q < m) {
                                    float tv = acc[am * 4 + na][h * 2 + cc] + ccj0[col] + civ;
                                    rowacc[rr] += ex2(tv);
                                    if (q > p) g_Dpair[c][p][q] = ex2(-tv);
                                }
                            }
                    }
            }

            __syncthreads();
            float* red = reinterpret_cast<float*>(sm + OFF_BH0);
#pragma unroll
            for (int am = 0; am < 4; ++am)
#pragma unroll
                for (int h = 0; h < 2; ++h) {
                    int mloc = warp_m * 64 + am * 16 + h * 8 + gq;
                    red[mloc * 17 + warp_n * 4 + t] = rowacc[am * 2 + h];
                }
            __syncthreads();
            if (tid < BM && ri + tid < m) {
                float s = 0.f;
#pragma unroll
                for (int q = 0; q < 16; ++q) s += red[tid * 17 + q];
                g_S[base + ri + tid] = s;
            }
        }
        return;
    }

    // ======== z strip path (fp16x2 exp epilogue) ========
    const int bi = blockIdx.x;
    const int gr = blockIdx.y;
    if (bi >= KT * gr + KT) return;
    const int lo = (bi > KT * gr) ? bi : KT * gr;
    const int hi = KT * gr + KT;

    const int r0 = bi * BM;
    const uint32_t bufB[2] = {smb + OFF_BH0, smb + OFF_BH1};
    float* ccjb[2] = {ccj0, ccj1};

    for (int s = tid; s < 2048; s += 256) {
        int row = s >> 4, ch = s & 15;
        CP_ASYNC16(smb + OFF_AH + (uint32_t)(row * PITCHB + ch * 16),
                   g_embA + (size_t)(r0 + row) * DIM + ch * 8);
    }
    if (tid < BM) rci[tid] = g_csqP[r0 + tid];

    for (int s = tid; s < 2048; s += 256) {
        int row = s >> 4, ch = s & 15;
        CP_ASYNC16(bufB[0] + (uint32_t)(row * PITCHB + ch * 16),
                   g_embB + (size_t)(lo * BM + row) * DIM + ch * 8);
    }
    if (tid < BM) ccj0[tid] = g_csqP[lo * BM + tid];
    CP_COMMIT();

    uint32_t rowacc2[8];
#pragma unroll
    for (int i = 0; i < 8; ++i) rowacc2[i] = 0u;

    for (int bj = lo; bj < hi; ++bj) {
        const int cur = (bj - lo) & 1;
        const int c0 = bj * BM;
        const bool offdiag = (bj != bi);

        if (bj + 1 < hi) {
            const int nc0 = (bj + 1) * BM;
            for (int s = tid; s < 2048; s += 256) {
                int row = s >> 4, ch = s & 15;
                CP_ASYNC16(bufB[cur ^ 1] + (uint32_t)(row * PITCHB + ch * 16),
                           g_embB + (size_t)(nc0 + row) * DIM + ch * 8);
            }
            if (tid < BM) ccjb[cur ^ 1][tid] = g_csqP[nc0 + tid];
            CP_COMMIT();
            CP_WAIT(1);
        } else {
            CP_WAIT(0);
        }
        __syncthreads();

        const uint32_t aBh = bufB[cur] + boff;
        const float* ccj = ccjb[cur];

        float acc[16][4];
#pragma unroll
        for (int i = 0; i < 16; ++i)
#pragma unroll
            for (int j = 0; j < 4; ++j) acc[i][j] = 0.f;

#pragma unroll
        for (int ks = 0; ks < 8; ++ks) {
            const uint32_t kb = (uint32_t)ks * 32;
            uint32_t ah[4][4], bh[2][4];
#pragma unroll
            for (int am = 0; am < 4; ++am)
                LDSM4(ah[am], aAh + (uint32_t)am * (16 * PITCHB) + kb);
#pragma unroll
            for (int bn = 0; bn < 2; ++bn)
                LDSM4(bh[bn], aBh + (uint32_t)bn * (16 * PITCHB) + kb);
#pragma unroll
            for (int am = 0; am < 4; ++am)
#pragma unroll
                for (int na = 0; na < 4; ++na) {
                    const int bn = na >> 1, p = (na & 1) * 2;
                    mma16816(acc[am * 4 + na], ah[am], bh[bn][p], bh[bn][p + 1]);
                }
        }

        // ---- fp16x2 epilogue: e = 2^(ci+cj-2*L2E*dot), row+col partials ----
        uint32_t colacc2[4] = {0u, 0u, 0u, 0u};
        float cjv[8];
#pragma unroll
        for (int na = 0; na < 4; ++na)
#pragma unroll
            for (int cc = 0; cc < 2; ++cc)
                cjv[na * 2 + cc] = ccj[warp_n * 32 + na * 8 + 2 * t + cc];

#pragma unroll
        for (int am = 0; am < 4; ++am)
#pragma unroll
            for (int h = 0; h < 2; ++h) {
                const int rr = am * 2 + h;
                const float civ = rci[warp_m * 64 + am * 16 + h * 8 + gq];
                float pc[8];
#pragma unroll
                for (int i = 0; i < 8; ++i) pc[i] = cjv[i] + civ;
                uint32_t racc2 = rowacc2[rr];
#pragma unroll
                for (int na = 0; na < 4; ++na) {
                    float tv0 = acc[am * 4 + na][h * 2 + 0] + pc[na * 2 + 0];
                    float tv1 = acc[am * 4 + na][h * 2 + 1] + pc[na * 2 + 1];
                    uint32_t e2 = pack_ex2_f16x2(tv1, tv0);   // lo=col cc0, hi=cc1
                    racc2 = hadd2u(racc2, e2);
                    colacc2[na] = hadd2u(colacc2[na], e2);
                }
                rowacc2[rr] = racc2;
            }

        if (offdiag) {
#pragma unroll
            for (int i = 0; i < 4; ++i)
#pragma unroll
                for (int off = 4; off < 32; off <<= 1)
                    colacc2[i] = hadd2u(colacc2[i],
                                        __shfl_xor_sync(0xffffffffu, colacc2[i], off));
            if (warp_m == 0 && gq == 0) {
#pragma unroll
                for (int na = 0; na < 4; ++na)
                    colred2[warp_n * 16 + na * 4 + t] = colacc2[na];
            }
        }
        __syncthreads();
        if (offdiag && warp_m == 1 && gq == 0) {
#pragma unroll
            for (int na = 0; na < 4; ++na) {
                uint32_t s2 = hadd2u(colred2[warp_n * 16 + na * 4 + t], colacc2[na]);
                float2 f = f16x2_to_f2(s2);
                int col = warp_n * 32 + na * 8 + 2 * t;
                *reinterpret_cast<float2*>(&g_Zmat[bi][c0 + col]) = f;
            }
        }
    }

    __syncthreads();
    float* red = reinterpret_cast<float*>(sm + OFF_BH0);
#pragma unroll
    for (int am = 0; am < 4; ++am)
#pragma unroll
        for (int h = 0; h < 2; ++h) {
            int mloc = warp_m * 64 + am * 16 + h * 8 + gq;
            float2 f = f16x2_to_f2(rowacc2[am * 2 + h]);
            red[mloc * 17 + warp_n * 4 + t] = f.x + f.y;
        }
    __syncthreads();
    if (tid < BM) {
        float s = 0.f;
#pragma unroll
        for (int q = 0; q < 16; ++q) s += red[tid * 17 + q];
        g_Zmat[NT + gr][r0 + tid] = s;
    }
}

// ---------------- pair kernel: warp per slot, lg2-based log1p ----------------
__global__ __launch_bounds__(256)
void pair3_kernel() {
    const int s    = (blockIdx.x * blockDim.x + threadIdx.x) >> 5;
    const int lane = threadIdx.x & 31;
    const int c = g_slotcls[s];
    const int p = s - g_off[c];
    const int m = g_off[c + 1] - g_off[c];

    float Za = g_Zmat[lane][s] + g_Zmat[lane + 32][s];
    if (lane < NGRP) Za += g_Zmat[NT + lane][s];
#pragma unroll
    for (int off = 16; off > 0; off >>= 1)
        Za += __shfl_xor_sync(0xffffffffu, Za, off);
    Za -= g_S[s];

    float lsum = 0.f;
    for (int q = p + 1 + lane; q < m; q += 32) {
        float x = fmaf(Za, g_Dpair[c][p][q], 1.0f);
        lsum += lg2(x);
    }
    lsum *= LN2;
#pragma unroll
    for (int off = 16; off > 0; off >>= 1)
        lsum += __shfl_xor_sync(0xffffffffu, lsum, off);
    if (lane == 0) g_rowsum[s] = lsum;
}

// ---------------- finish: per-class means + final scalar, one block ----------------
__global__ __launch_bounds__(512)
void finish_kernel(float* __restrict__ out) {
    __shared__ float smean[NCLS];
    __shared__ int   svalid[NCLS];
    const int tid = threadIdx.x, warp = tid >> 5, lane = tid & 31;

    for (int c = warp * 4; c < warp * 4 + 4; ++c) {
        const int base = g_off[c];
        const int m = g_off[c + 1] - base;
        float s = 0.f;
        for (int q = lane; q < m; q += 32) s += g_rowsum[base + q];
#pragma unroll
        for (int off = 16; off > 0; off >>= 1)
            s += __shfl_xor_sync(0xffffffffu, s, off);
        if (lane == 0) {
            if (m >= 2) {
                smean[c]  = s / (0.5f * (float)m * (float)(m - 1));
                svalid[c] = 1;
            } else { smean[c] = 0.f; svalid[c] = 0; }
        }
    }
    __syncthreads();
    if (warp == 0) {
        float s  = smean[lane] + smean[lane + 32];
        int   nv = svalid[lane] + svalid[lane + 32];
#pragma unroll
        for (int off = 16; off > 0; off >>= 1) {
            s  += __shfl_xor_sync(0xffffffffu, s, off);
            nv += __shfl_xor_sync(0xffffffffu, nv, off);
        }
        if (lane == 0) out[0] = s / (float)(nv > 0 ? nv : 1);
    }
}

// ---------------- launch ----------------
extern "C" void kernel_launch(void* const* d_in, const int* in_sizes, int n_in,
                              void* d_out, int out_size) {
    const float* emb    = (const float*)d_in[0];
    const int*   labels = (const int*)d_in[1];
    float*       out    = (float*)d_out;

    static bool attr_set = false;
    if (!attr_set) {
        cudaFuncSetAttribute(zc_kernel, cudaFuncAttributeMaxDynamicSharedMemorySize, Z_SMEM_Z);
        attr_set = true;
    }

    classes_kernel<<<NCLS, 256>>>(labels);
    prep_kernel<<<N / 8, 256>>>(emb, labels);
    zc_kernel<<<dim3(NT, NGRP + 1), 256, Z_SMEM_Z>>>();
    pair3_kernel<<<N / 8, 256>>>();
    finish_kernel<<<1, 512>>>(out);
}